// round 13
// baseline (speedup 1.0000x reference)
#include <cuda_runtime.h>
#include <cuda_bf16.h>
#include <math.h>
#include <stdint.h>

// ---------------- problem constants ----------------
#define B_TOK 4096
#define DIN   512
#define PP    1024
#define HH    2048
#define EE    8
#define HSH   4096
#define OUTN  29
#define CAP   4096

// ---------------- big GEMM config (proven r8/r10/r11) ----------------
#define BM 128
#define BN 256
#define BKC 32
#define ROWB 80
#define OFF_AH 0
#define OFF_AL (128 * ROWB)
#define OFF_BH (256 * ROWB)
#define OFF_BL (256 * ROWB + 256 * ROWB)
#define STAGE_BYTES (768 * ROWB)
#define NSTAGE 3
#define SMEM_BYTES (NSTAGE * STAGE_BYTES)
#define NTHR 512

// ---------------- small GEMM config (128x128, 2 CTAs/SM, 2-stage) ----------------
#define BN2 128
#define OFF2_AH 0
#define OFF2_AL (128 * ROWB)
#define OFF2_BH (256 * ROWB)
#define OFF2_BL (384 * ROWB)
#define STAGE2_BYTES (512 * ROWB)          // 40960
#define SMEM2_BYTES (2 * STAGE2_BYTES)     // 81920

// ---------------- PTX helpers ----------------
__device__ __forceinline__ uint32_t smem_u32(const void* p) {
    uint32_t a;
    asm("{ .reg .u64 t; cvta.to.shared.u64 t, %1; cvt.u32.u64 %0, t; }" : "=r"(a) : "l"(p));
    return a;
}
#define CP16(dst, src) asm volatile("cp.async.cg.shared.global [%0], [%1], 16;" :: "r"(dst), "l"(src) : "memory")
#define CP_COMMIT()    asm volatile("cp.async.commit_group;" ::: "memory")

#define LDSM4(r, addr) \
    asm volatile("ldmatrix.sync.aligned.m8n8.x4.shared.b16 {%0,%1,%2,%3}, [%4];" \
        : "=r"((r)[0]), "=r"((r)[1]), "=r"((r)[2]), "=r"((r)[3]) : "r"(addr))

#define MMA_BF16(c, a, b0, b1) \
    asm volatile("mma.sync.aligned.m16n8k16.row.col.f32.bf16.bf16.f32 " \
        "{%0,%1,%2,%3}, {%4,%5,%6,%7}, {%8,%9}, {%0,%1,%2,%3};" \
        : "+f"((c)[0]), "+f"((c)[1]), "+f"((c)[2]), "+f"((c)[3]) \
        : "r"((a)[0]), "r"((a)[1]), "r"((a)[2]), "r"((a)[3]), "r"(b0), "r"(b1))

// ---------------- scratch (device globals) ----------------
#define DEV __device__ __align__(128)
DEV __nv_bfloat16 g_x_hi [B_TOK * DIN],   g_x_lo [B_TOK * DIN];
DEV __nv_bfloat16 g_p_hi [B_TOK * PP],    g_p_lo [B_TOK * PP];
DEV float         g_p32  [B_TOK * PP];
DEV __nv_bfloat16 g_h_hi [(size_t)EE * CAP * HH], g_h_lo [(size_t)EE * CAP * HH];
DEV float         g_eo32 [(size_t)EE * CAP * PP];
DEV float         g_moe  [B_TOK * PP];
DEV __nv_bfloat16 g_su_hi[(size_t)B_TOK * HSH],   g_su_lo[(size_t)B_TOK * HSH];
DEV __nv_bfloat16 g_cb_hi[B_TOK * PP],    g_cb_lo[B_TOK * PP];
DEV __nv_bfloat16 g_h1_hi[B_TOK * HH],    g_h1_lo[B_TOK * HH];
DEV float         g_h232 [B_TOK * HH];
DEV __nv_bfloat16 g_wp_hi [PP * DIN],     g_wp_lo [PP * DIN];
DEV __nv_bfloat16 g_w1_hi [EE * HH * PP], g_w1_lo [EE * HH * PP];
DEV __nv_bfloat16 g_w2_hi [EE * PP * HH], g_w2_lo [EE * PP * HH];
DEV __nv_bfloat16 g_guw_hi[(size_t)2 * HSH * PP], g_guw_lo[(size_t)2 * HSH * PP];
DEV float         g_gub   [2 * HSH];
DEV __nv_bfloat16 g_sdw_hi[PP * HSH],     g_sdw_lo[PP * HSH];
DEV __nv_bfloat16 g_m1_hi [HH * PP],      g_m1_lo [HH * PP];
DEV __nv_bfloat16 g_m2_hi [HH * HH],      g_m2_lo [HH * HH];
DEV int   g_counts[EE];
DEV int   g_slot_token[EE * CAP];
DEV int   g_pair_slot[B_TOK * 2];
DEV float g_pair_gate[B_TOK * 2];

__device__ __forceinline__ float silu_f(float x) { return x / (1.0f + expf(-x)); }

// ---------------- big-config stage fill (512 threads) ----------------
template<bool GATHER>
__device__ __forceinline__ void fill_stage(uint32_t st, int tid,
    const char* Ah, const char* Al, const char* Bh, const char* Bl,
    size_t Kb, long rowA0, long rowB0, const int* __restrict__ tokRow, size_t kByte)
{
    {
        int row = tid >> 2, ch = tid & 3;
        uint32_t d = st + row * ROWB + ch * 16;
        long arow = GATHER ? (long)tokRow[row] : (rowA0 + row);
        size_t s = (size_t)arow * Kb + kByte + ch * 16;
        CP16(d + OFF_AH, Ah + s);
        CP16(d + OFF_AL, Al + s);
    }
#pragma unroll
    for (int i = 0; i < 2; i++) {
        int p = tid + (i << 9);
        int row = p >> 2, ch = p & 3;
        uint32_t d = st + row * ROWB + ch * 16;
        size_t s = (size_t)(rowB0 + row) * Kb + kByte + ch * 16;
        CP16(d + OFF_BH, Bh + s);
        CP16(d + OFF_BL, Bl + s);
    }
    CP_COMMIT();
}

// ---------------- big GEMM: 128x256, 16 warps, 3-stage ----------------
// MODE: 0=+bias 1=silu(+bias) 3=(+bias)+extra 4=fused SwiGLU pairs
template<int MODE, bool GATHER>
__global__ __launch_bounds__(NTHR, 1)
void mm_gemm(const __nv_bfloat16* __restrict__ Ahi, const __nv_bfloat16* __restrict__ Alo,
             const __nv_bfloat16* __restrict__ Bhi, const __nv_bfloat16* __restrict__ Blo,
             const float* __restrict__ bias, const float* __restrict__ extra,
             float* __restrict__ C32, __nv_bfloat16* __restrict__ Chi,
             __nv_bfloat16* __restrict__ Clo,
             const int* __restrict__ counts, const int* __restrict__ stok,
             int capRows, int N, int K)
{
    const int z  = blockIdx.z;
    const int m0 = blockIdx.y * BM;
    const int n0 = blockIdx.x * BN;
    int cnt = capRows;
    if (counts) { cnt = counts[z]; if (m0 >= cnt) return; }

    extern __shared__ __align__(128) char smem[];
    const uint32_t sb = smem_u32(smem);
    const int tid = threadIdx.x, lane = tid & 31, wid = tid >> 5;
    const int warp_m = wid & 3;
    const int warp_n = wid >> 2;

    const size_t Kb = (size_t)K * 2;
    const long rowA0 = (long)z * capRows + m0;
    const long rowB0 = (long)z * N + n0;
    const int* tokRow = GATHER ? (stok + z * CAP + m0) : nullptr;
    const int  C = K / BKC;

    float acc[2][8][4];
#pragma unroll
    for (int i = 0; i < 2; i++)
#pragma unroll
        for (int j = 0; j < 8; j++)
#pragma unroll
            for (int q = 0; q < 4; q++) acc[i][j][q] = 0.f;

    const char* Ah = (const char*)Ahi; const char* Al = (const char*)Alo;
    const char* Bh = (const char*)Bhi; const char* Bl = (const char*)Blo;

    fill_stage<GATHER>(sb, tid, Ah, Al, Bh, Bl, Kb, rowA0, rowB0, tokRow, 0);
    if (C > 1) fill_stage<GATHER>(sb + STAGE_BYTES, tid, Ah, Al, Bh, Bl, Kb, rowA0, rowB0, tokRow, 64);

    const int lm = lane & 15;
    const int lkb = (lane >> 4) << 4;

    for (int c = 0; c < C; c++) {
        if (c + 2 < C) asm volatile("cp.async.wait_group 1;" ::: "memory");
        else           asm volatile("cp.async.wait_group 0;" ::: "memory");
        __syncthreads();
        if (c + 2 < C)
            fill_stage<GATHER>(sb + ((c + 2) % NSTAGE) * STAGE_BYTES, tid, Ah, Al, Bh, Bl,
                               Kb, rowA0, rowB0, tokRow, (size_t)(c + 2) * 64);

        const uint32_t stg = sb + (c % NSTAGE) * STAGE_BYTES;
#pragma unroll
        for (int kk = 0; kk < 2; kk++) {
            const uint32_t kb = kk * 32 + lkb;
            uint32_t a_h[2][4], a_l[2][4];
#pragma unroll
            for (int mt = 0; mt < 2; mt++) {
                uint32_t ad = stg + (warp_m * 32 + mt * 16 + lm) * ROWB + kb;
                LDSM4(a_h[mt], ad + OFF_AH);
                LDSM4(a_l[mt], ad + OFF_AL);
            }
#pragma unroll
            for (int n2 = 0; n2 < 4; n2++) {
                uint32_t b_h[4], b_l[4];
                uint32_t bd = stg + (warp_n * 64 + n2 * 16 + lm) * ROWB + kb;
                LDSM4(b_h, bd + OFF_BH);
                LDSM4(b_l, bd + OFF_BL);
#pragma unroll
                for (int mt = 0; mt < 2; mt++)
#pragma unroll
                    for (int o = 0; o < 2; o++) {
                        const int nt = n2 * 2 + o;
                        MMA_BF16(acc[mt][nt], a_h[mt], b_h[o], b_h[o + 2]);
                        MMA_BF16(acc[mt][nt], a_h[mt], b_l[o], b_l[o + 2]);
                        MMA_BF16(acc[mt][nt], a_l[mt], b_h[o], b_h[o + 2]);
                    }
            }
        }
    }

    const float* biasz = bias + (size_t)z * N;
#pragma unroll
    for (int mt = 0; mt < 2; mt++) {
#pragma unroll
        for (int half = 0; half < 2; half++) {
            const int rtile = warp_m * 32 + mt * 16 + (lane >> 2) + half * 8;
            if (m0 + rtile >= cnt) continue;
            const size_t gr = (size_t)z * capRows + m0 + rtile;
#pragma unroll
            for (int nt = 0; nt < 8; nt++) {
                const int col = n0 + warp_n * 64 + nt * 8 + (lane & 3) * 2;
                float v0 = acc[mt][nt][half * 2 + 0] + biasz[col];
                float v1 = acc[mt][nt][half * 2 + 1] + biasz[col + 1];
                if (MODE == 4) {
                    float w = silu_f(v0) * v1;
                    __nv_bfloat16 h = __float2bfloat16(w);
                    const size_t o = gr * (size_t)(N >> 1) + (col >> 1);
                    Chi[o] = h;
                    Clo[o] = __float2bfloat16(w - __bfloat162float(h));
                    continue;
                }
                if (MODE == 1) { v0 = silu_f(v0); v1 = silu_f(v1); }
                if (MODE == 3) {
                    const float2 e = *(const float2*)&extra[gr * N + col];
                    v0 += e.x; v1 += e.y;
                }
                if (C32) { float2 w = {v0, v1}; *(float2*)&C32[gr * N + col] = w; }
                if (Chi) {
                    __nv_bfloat16 h0 = __float2bfloat16(v0);
                    __nv_bfloat16 h1 = __float2bfloat16(v1);
                    __nv_bfloat162 hp; hp.x = h0; hp.y = h1;
                    *(__nv_bfloat162*)&Chi[gr * N + col] = hp;
                    __nv_bfloat162 lp;
                    lp.x = __float2bfloat16(v0 - __bfloat162float(h0));
                    lp.y = __float2bfloat16(v1 - __bfloat162float(h1));
                    *(__nv_bfloat162*)&Clo[gr * N + col] = lp;
                }
            }
        }
    }
}

// ---------------- small-config stage fill (256 threads, A+B 128 rows each) ----------------
__device__ __forceinline__ void fill_stage2(uint32_t st, int tid,
    const char* Ah, const char* Al, const char* Bh, const char* Bl,
    size_t Kb, long rowA0, long rowB0, size_t kByte)
{
#pragma unroll
    for (int i = 0; i < 2; i++) {
        int p = tid + (i << 8);
        int row = p >> 2, ch = p & 3;
        uint32_t d = st + row * ROWB + ch * 16;
        size_t sa = (size_t)(rowA0 + row) * Kb + kByte + ch * 16;
        CP16(d + OFF2_AH, Ah + sa);
        CP16(d + OFF2_AL, Al + sa);
        size_t sbo = (size_t)(rowB0 + row) * Kb + kByte + ch * 16;
        CP16(d + OFF2_BH, Bh + sbo);
        CP16(d + OFF2_BL, Bl + sbo);
    }
    CP_COMMIT();
}

// ---------------- small GEMM: 128x128, 8 warps (warp 64x32), 2-stage, 2 CTAs/SM ----------------
// MODE: 0=+bias 1=silu(+bias) 3=(+bias)+extra
template<int MODE>
__global__ __launch_bounds__(256, 2)
void mm_gemm2(const __nv_bfloat16* __restrict__ Ahi, const __nv_bfloat16* __restrict__ Alo,
              const __nv_bfloat16* __restrict__ Bhi, const __nv_bfloat16* __restrict__ Blo,
              const float* __restrict__ bias, const float* __restrict__ extra,
              float* __restrict__ C32, __nv_bfloat16* __restrict__ Chi,
              __nv_bfloat16* __restrict__ Clo, int N, int K)
{
    const int m0 = blockIdx.y * BM;
    const int n0 = blockIdx.x * BN2;

    extern __shared__ __align__(128) char smem[];
    const uint32_t sb = smem_u32(smem);
    const int tid = threadIdx.x, lane = tid & 31, wid = tid >> 5;
    const int warp_m = wid & 1;       // 2 warps over M (64 rows)
    const int warp_n = wid >> 1;      // 4 warps over N (32 cols)

    const size_t Kb = (size_t)K * 2;
    const int C = K / BKC;

    float acc[4][4][4];
#pragma unroll
    for (int i = 0; i < 4; i++)
#pragma unroll
        for (int j = 0; j < 4; j++)
#pragma unroll
            for (int q = 0; q < 4; q++) acc[i][j][q] = 0.f;

    const char* Ah = (const char*)Ahi; const char* Al = (const char*)Alo;
    const char* Bh = (const char*)Bhi; const char* Bl = (const char*)Blo;

    fill_stage2(sb, tid, Ah, Al, Bh, Bl, Kb, m0, n0, 0);
    if (C > 1) fill_stage2(sb + STAGE2_BYTES, tid, Ah, Al, Bh, Bl, Kb, m0, n0, 64);

    const int lm = lane & 15;
    const int lkb = (lane >> 4) << 4;

    for (int c = 0; c < C; c++) {
        if (c + 1 < C) asm volatile("cp.async.wait_group 1;" ::: "memory");
        else           asm volatile("cp.async.wait_group 0;" ::: "memory");
        __syncthreads();

        const uint32_t stg = sb + (c & 1) * STAGE2_BYTES;
#pragma unroll
        for (int kk = 0; kk < 2; kk++) {
            const uint32_t kb = kk * 32 + lkb;
            uint32_t a_h[4][4], a_l[4][4], b_h[2][4], b_l[2][4];
#pragma unroll
            for (int mt = 0; mt < 4; mt++) {
                uint32_t ad = stg + (warp_m * 64 + mt * 16 + lm) * ROWB + kb;
                LDSM4(a_h[mt], ad + OFF2_AH);
                LDSM4(a_l[mt], ad + OFF2_AL);
            }
#pragma unroll
            for (int nt2 = 0; nt2 < 2; nt2++) {
                uint32_t bd = stg + (warp_n * 32 + nt2 * 16 + lm) * ROWB + kb;
                LDSM4(b_h[nt2], bd + OFF2_BH);
                LDSM4(b_l[nt2], bd + OFF2_BL);
            }
#pragma unroll
            for (int mt = 0; mt < 4; mt++)
#pragma unroll
                for (int nt = 0; nt < 4; nt++) {
                    const int n2 = nt >> 1, o = nt & 1;
                    MMA_BF16(acc[mt][nt], a_h[mt], b_h[n2][o], b_h[n2][o + 2]);
                    MMA_BF16(acc[mt][nt], a_h[mt], b_l[n2][o], b_l[n2][o + 2]);
                    MMA_BF16(acc[mt][nt], a_l[mt], b_h[n2][o], b_h[n2][o + 2]);
                }
        }
        __syncthreads();
        if (c + 2 < C)
            fill_stage2(sb + (c & 1) * STAGE2_BYTES, tid, Ah, Al, Bh, Bl,
                        Kb, m0, n0, (size_t)(c + 2) * 64);
    }

    // epilogue
#pragma unroll
    for (int mt = 0; mt < 4; mt++) {
#pragma unroll
        for (int half = 0; half < 2; half++) {
            const int r = m0 + warp_m * 64 + mt * 16 + (lane >> 2) + half * 8;
            const size_t gr = (size_t)r;
#pragma unroll
            for (int nt = 0; nt < 4; nt++) {
                const int col = n0 + warp_n * 32 + nt * 8 + (lane & 3) * 2;
                float v0 = acc[mt][nt][half * 2 + 0] + bias[col];
                float v1 = acc[mt][nt][half * 2 + 1] + bias[col + 1];
                if (MODE == 1) { v0 = silu_f(v0); v1 = silu_f(v1); }
                if (MODE == 3) {
                    const float2 e = *(const float2*)&extra[gr * N + col];
                    v0 += e.x; v1 += e.y;
                }
                if (C32) { float2 w = {v0, v1}; *(float2*)&C32[gr * N + col] = w; }
                if (Chi) {
                    __nv_bfloat16 h0 = __float2bfloat16(v0);
                    __nv_bfloat16 h1 = __float2bfloat16(v1);
                    __nv_bfloat162 hp; hp.x = h0; hp.y = h1;
                    *(__nv_bfloat162*)&Chi[gr * N + col] = hp;
                    __nv_bfloat162 lp;
                    lp.x = __float2bfloat16(v0 - __bfloat162float(h0));
                    lp.y = __float2bfloat16(v1 - __bfloat162float(h1));
                    *(__nv_bfloat162*)&Clo[gr * N + col] = lp;
                }
            }
        }
    }
}

// ---------------- small kernels ----------------
__global__ void conv_split_k(const float* __restrict__ in, __nv_bfloat16* __restrict__ hi,
                             __nv_bfloat16* __restrict__ lo, size_t n)
{
    size_t i = (size_t)blockIdx.x * blockDim.x + threadIdx.x;
    if (i >= n) return;
    float v = in[i];
    __nv_bfloat16 h = __float2bfloat16(v);
    hi[i] = h;
    lo[i] = __float2bfloat16(v - __bfloat162float(h));
}

template<int RMUL>
__global__ __launch_bounds__(256)
void convT2_k(const float* __restrict__ W, __nv_bfloat16* __restrict__ hi,
              __nv_bfloat16* __restrict__ lo, int K, int N, int radd)
{
    __shared__ float t[32][129];
    const int k0 = blockIdx.y * 32, n0 = blockIdx.x * 128;
    const float* Wz = W + (size_t)blockIdx.z * K * N;
    const int tid = threadIdx.x;
    {
        const int c = tid & 127;
        for (int r = tid >> 7; r < 32; r += 2)
            t[r][c] = Wz[(size_t)(k0 + r) * N + n0 + c];
    }
    __syncthreads();
    const size_t zbase = (size_t)blockIdx.z * N * RMUL;
    for (int idx = tid; idx < 128 * 16; idx += 256) {
        const int n = idx >> 4, kp = idx & 15;
        float v0 = t[kp * 2][n], v1 = t[kp * 2 + 1][n];
        __nv_bfloat16 h0 = __float2bfloat16(v0), h1 = __float2bfloat16(v1);
        __nv_bfloat162 hp; hp.x = h0; hp.y = h1;
        __nv_bfloat162 lp;
        lp.x = __float2bfloat16(v0 - __bfloat162float(h0));
        lp.y = __float2bfloat16(v1 - __bfloat162float(h1));
        const size_t orow = zbase + (size_t)(n0 + n) * RMUL + radd;
        const size_t o = orow * K + k0 + kp * 2;
        *(__nv_bfloat162*)&hi[o] = hp;
        *(__nv_bfloat162*)&lo[o] = lp;
    }
}

__global__ void ileave_bias_k(const float* __restrict__ a, const float* __restrict__ b,
                              float* __restrict__ o, int n)
{
    int i = blockIdx.x * 256 + threadIdx.x;
    if (i < n) { o[2 * i] = a[i]; o[2 * i + 1] = b[i]; }
}

__global__ void zero_counts_k(int* counts) { if (threadIdx.x < EE) counts[threadIdx.x] = 0; }

__global__ void router_k(const float* __restrict__ p, const float* __restrict__ Wg,
                         int* __restrict__ counts, int* __restrict__ slot_token,
                         int* __restrict__ pair_slot, float* __restrict__ pair_gate)
{
    const int t = blockIdx.x;
    const int tid = threadIdx.x; // 128
    __shared__ float red[EE][128];
    float acc[EE];
#pragma unroll
    for (int e = 0; e < EE; e++) acc[e] = 0.f;
    const float* pr = p + (size_t)t * PP;
    for (int j = tid; j < PP; j += 128) {
        float pv = pr[j];
        const float* wg = Wg + (size_t)j * EE;
#pragma unroll
        for (int e = 0; e < EE; e++) acc[e] += pv * wg[e];
    }
#pragma unroll
    for (int e = 0; e < EE; e++) red[e][tid] = acc[e];
    __syncthreads();
    if (tid == 0) {
        float logit[EE];
        for (int e = 0; e < EE; e++) {
            float s = 0.f;
            for (int i = 0; i < 128; i++) s += red[e][i];
            logit[e] = s;
        }
        int i0 = 0;
        for (int e = 1; e < EE; e++) if (logit[e] > logit[i0]) i0 = e;
        int i1 = (i0 == 0) ? 1 : 0;
        for (int e = 0; e < EE; e++) {
            if (e == i0) continue;
            if (logit[e] > logit[i1]) i1 = e;
        }
        float g0 = 1.f / (1.f + expf(logit[i1] - logit[i0]));
        float g1 = 1.f - g0;
        int s0 = atomicAdd(&counts[i0], 1);
        int s1 = atomicAdd(&counts[i1], 1);
        slot_token[i0 * CAP + s0] = t;
        slot_token[i1 * CAP + s1] = t;
        pair_slot[2 * t]     = i0 * CAP + s0;
        pair_slot[2 * t + 1] = i1 * CAP + s1;
        pair_gate[2 * t]     = g0;
        pair_gate[2 * t + 1] = g1;
    }
}

__global__ void combine_k(const float* __restrict__ eo, const int* __restrict__ pair_slot,
                          const float* __restrict__ pair_gate, float* __restrict__ moe)
{
    int idx = blockIdx.x * blockDim.x + threadIdx.x;
    if (idx >= B_TOK * PP) return;
    int t = idx >> 10, j = idx & (PP - 1);
    int s0 = pair_slot[2 * t], s1 = pair_slot[2 * t + 1];
    float g0 = pair_gate[2 * t], g1 = pair_gate[2 * t + 1];
    moe[idx] = g0 * eo[(size_t)s0 * PP + j] + g1 * eo[(size_t)s1 * PP + j];
}

// ---------------- head: tiled, 32 tokens per block ----------------
#define HKC 128
__global__ __launch_bounds__(928)
void head2_k(const float* __restrict__ hid2, const float* __restrict__ head_w,
             const float* __restrict__ head_b, float* __restrict__ out)
{
    __shared__ float hs[32 * HKC];
    __shared__ float ws[HKC * 30];
    const int tid = threadIdx.x;
    const int tok0 = blockIdx.x * 32;
    const int tokl = tid / OUTN;
    const int o    = tid % OUTN;
    float acc = 0.f;

    for (int kc = 0; kc < HH; kc += HKC) {
        for (int i = tid; i < 32 * HKC; i += 928)
            hs[i] = hid2[(size_t)(tok0 + (i >> 7)) * HH + kc + (i & (HKC - 1))];
        for (int i = tid; i < HKC * OUTN; i += 928) {
            int k = i / OUTN, oo = i % OUTN;
            ws[k * 30 + oo] = head_w[(size_t)(kc + k) * OUTN + oo];
        }
        __syncthreads();
        const float* hrow = hs + tokl * HKC;
#pragma unroll 4
        for (int k = 0; k < HKC; k++)
            acc += hrow[k] * ws[k * 30 + o];
        __syncthreads();
    }
    out[(size_t)(tok0 + tokl) * OUTN + o] = acc + head_b[o];
}

// ---------------- launch ----------------
template <typename T>
static T* symaddr(const void* sym) { void* p = nullptr; cudaGetSymbolAddress(&p, sym); return (T*)p; }

extern "C" void kernel_launch(void* const* d_in, const int* in_sizes, int n_in,
                              void* d_out, int out_size)
{
    const float* x      = (const float*)d_in[0];
    const float* Wproj  = (const float*)d_in[1];
    const float* bproj  = (const float*)d_in[2];
    const float* Wg     = (const float*)d_in[3];
    const float* W1     = (const float*)d_in[4];
    const float* b1     = (const float*)d_in[5];
    const float* W2     = (const float*)d_in[6];
    const float* b2     = (const float*)d_in[7];
    const float* sg_w   = (const float*)d_in[8];
    const float* sg_b   = (const float*)d_in[9];
    const float* su_w   = (const float*)d_in[10];
    const float* su_b   = (const float*)d_in[11];
    const float* sd_w   = (const float*)d_in[12];
    const float* sd_b   = (const float*)d_in[13];
    const float* m1_w   = (const float*)d_in[14];
    const float* m1_b   = (const float*)d_in[15];
    const float* m2_w   = (const float*)d_in[16];
    const float* m2_b   = (const float*)d_in[17];
    const float* head_w = (const float*)d_in[18];
    const float* head_b = (const float*)d_in[19];
    float* out = (float*)d_out;

    static cudaStream_t s1 = nullptr;
    static cudaEvent_t evFork, evP, evW1, evW2, evSw;
    if (!s1) {
        cudaStreamCreateWithFlags(&s1, cudaStreamNonBlocking);
        cudaEventCreateWithFlags(&evFork, cudaEventDisableTiming);
        cudaEventCreateWithFlags(&evP,    cudaEventDisableTiming);
        cudaEventCreateWithFlags(&evW1,   cudaEventDisableTiming);
        cudaEventCreateWithFlags(&evW2,   cudaEventDisableTiming);
        cudaEventCreateWithFlags(&evSw,   cudaEventDisableTiming);
        cudaFuncSetAttribute(mm_gemm<0, false>, cudaFuncAttributeMaxDynamicSharedMemorySize, SMEM_BYTES);
        cudaFuncSetAttribute(mm_gemm<1, false>, cudaFuncAttributeMaxDynamicSharedMemorySize, SMEM_BYTES);
        cudaFuncSetAttribute(mm_gemm<4, false>, cudaFuncAttributeMaxDynamicSharedMemorySize, SMEM_BYTES);
        cudaFuncSetAttribute(mm_gemm<1, true>,  cudaFuncAttributeMaxDynamicSharedMemorySize, SMEM_BYTES);
        cudaFuncSetAttribute(mm_gemm2<0>, cudaFuncAttributeMaxDynamicSharedMemorySize, SMEM2_BYTES);
        cudaFuncSetAttribute(mm_gemm2<1>, cudaFuncAttributeMaxDynamicSharedMemorySize, SMEM2_BYTES);
        cudaFuncSetAttribute(mm_gemm2<3>, cudaFuncAttributeMaxDynamicSharedMemorySize, SMEM2_BYTES);
    }

    __nv_bfloat16 *x_hi = symaddr<__nv_bfloat16>(g_x_hi),  *x_lo = symaddr<__nv_bfloat16>(g_x_lo);
    __nv_bfloat16 *p_hi = symaddr<__nv_bfloat16>(g_p_hi),  *p_lo = symaddr<__nv_bfloat16>(g_p_lo);
    float *p32  = symaddr<float>(g_p32);
    __nv_bfloat16 *h_hi  = symaddr<__nv_bfloat16>(g_h_hi),  *h_lo  = symaddr<__nv_bfloat16>(g_h_lo);
    float *eo32 = symaddr<float>(g_eo32);
    float *moe  = symaddr<float>(g_moe);
    __nv_bfloat16 *su_hi = symaddr<__nv_bfloat16>(g_su_hi), *su_lo = symaddr<__nv_bfloat16>(g_su_lo);
    __nv_bfloat16 *cb_hi = symaddr<__nv_bfloat16>(g_cb_hi), *cb_lo = symaddr<__nv_bfloat16>(g_cb_lo);
    __nv_bfloat16 *h1_hi = symaddr<__nv_bfloat16>(g_h1_hi), *h1_lo = symaddr<__nv_bfloat16>(g_h1_lo);
    float *h232 = symaddr<float>(g_h232);
    __nv_bfloat16 *wp_hi = symaddr<__nv_bfloat16>(g_wp_hi), *wp_lo = symaddr<__nv_bfloat16>(g_wp_lo);
    __nv_bfloat16 *w1_hi = symaddr<__nv_bfloat16>(g_w1_hi), *w1_lo = symaddr<__nv_bfloat16>(g_w1_lo);
    __nv_bfloat16 *w2_hi = symaddr<__nv_bfloat16>(g_w2_hi), *w2_lo = symaddr<__nv_bfloat16>(g_w2_lo);
    __nv_bfloat16 *guw_hi = symaddr<__nv_bfloat16>(g_guw_hi), *guw_lo = symaddr<__nv_bfloat16>(g_guw_lo);
    float *gub = symaddr<float>(g_gub);
    __nv_bfloat16 *sdw_hi = symaddr<__nv_bfloat16>(g_sdw_hi), *sdw_lo = symaddr<__nv_bfloat16>(g_sdw_lo);
    __nv_bfloat16 *m1_hi = symaddr<__nv_bfloat16>(g_m1_hi), *m1_lo = symaddr<__nv_bfloat16>(g_m1_lo);
    __nv_bfloat16 *m2_hi = symaddr<__nv_bfloat16>(g_m2_hi), *m2_lo = symaddr<__nv_bfloat16>(g_m2_lo);
    int *counts = symaddr<int>(g_counts);
    int *stok   = symaddr<int>(g_slot_token);
    int *pslot  = symaddr<int>(g_pair_slot);
    float *pgate = symaddr<float>(g_pair_gate);

    // ---- fork side stream ----
    cudaEventRecord(evFork, 0);
    cudaStreamWaitEvent(s1, evFork, 0);

    // s1: heavy weight transposes (overlap proj GEMM + router)
    convT2_k<1><<<dim3(HH / 128, PP / 32, EE),  256, 0, s1>>>(W1, w1_hi, w1_lo, PP, HH, 0);
    cudaEventRecord(evW1, s1);
    convT2_k<1><<<dim3(PP / 128, HH / 32, EE),  256, 0, s1>>>(W2, w2_hi, w2_lo, HH, PP, 0);
    cudaEventRecord(evW2, s1);
    convT2_k<2><<<dim3(HSH / 128, PP / 32, 1),  256, 0, s1>>>(sg_w, guw_hi, guw_lo, PP, HSH, 0);
    convT2_k<2><<<dim3(HSH / 128, PP / 32, 1),  256, 0, s1>>>(su_w, guw_hi, guw_lo, PP, HSH, 1);
    ileave_bias_k<<<(HSH + 255) / 256, 256, 0, s1>>>(sg_b, su_b, gub, HSH);
    convT2_k<1><<<dim3(PP / 128, HSH / 32, 1),  256, 0, s1>>>(sd_w, sdw_hi, sdw_lo, HSH, PP, 0);
    convT2_k<1><<<dim3(HH / 128, PP / 32, 1),   256, 0, s1>>>(m1_w, m1_hi, m1_lo, PP, HH, 0);
    convT2_k<1><<<dim3(HH / 128, HH / 32, 1),   256, 0, s1>>>(m2_w, m2_hi, m2_lo, HH, HH, 0);

    // main: input split + proj GEMM + router
    conv_split_k<<<(B_TOK * DIN + 255) / 256, 256>>>(x, x_hi, x_lo, (size_t)B_TOK * DIN);
    convT2_k<1><<<dim3(PP / 128, DIN / 32, 1),  256>>>(Wproj, wp_hi, wp_lo, DIN, PP, 0);
    mm_gemm<0, false><<<dim3(PP / BN, B_TOK / BM, 1), NTHR, SMEM_BYTES>>>(
        x_hi, x_lo, wp_hi, wp_lo, bproj, nullptr, p32, p_hi, p_lo,
        nullptr, nullptr, B_TOK, PP, DIN);
    cudaEventRecord(evP, 0);
    zero_counts_k<<<1, 32>>>(counts);
    router_k<<<B_TOK, 128>>>(p32, Wg, counts, stok, pslot, pgate);

    // s1: fused shared SwiGLU (overlaps expert chain)
    cudaStreamWaitEvent(s1, evP, 0);
    mm_gemm<4, false><<<dim3((2 * HSH) / BN, B_TOK / BM, 1), NTHR, SMEM_BYTES, s1>>>(
        p_hi, p_lo, guw_hi, guw_lo, gub, nullptr, nullptr, su_hi, su_lo,
        nullptr, nullptr, B_TOK, 2 * HSH, PP);
    cudaEventRecord(evSw, s1);

    // main: expert chain
    cudaStreamWaitEvent(0, evW1, 0);
    mm_gemm<1, true><<<dim3(HH / BN, CAP / BM, EE), NTHR, SMEM_BYTES>>>(
        p_hi, p_lo, w1_hi, w1_lo, b1, nullptr, nullptr, h_hi, h_lo,
        counts, stok, CAP, HH, PP);
    cudaStreamWaitEvent(0, evW2, 0);
    mm_gemm<0, false><<<dim3(PP / BN, CAP / BM, EE), NTHR, SMEM_BYTES>>>(
        h_hi, h_lo, w2_hi, w2_lo, b2, nullptr, eo32, nullptr, nullptr,
        counts, nullptr, CAP, PP, HH);
    combine_k<<<(B_TOK * PP + 255) / 256, 256>>>(eo32, pslot, pgate, moe);

    // join, then end-chain on small-tile config (2 CTAs/SM, halved tail quanta)
    cudaStreamWaitEvent(0, evSw, 0);
    mm_gemm2<3><<<dim3(PP / BN2, B_TOK / BM), 256, SMEM2_BYTES>>>(
        su_hi, su_lo, sdw_hi, sdw_lo, sd_b, moe, nullptr, cb_hi, cb_lo, PP, HSH);
    mm_gemm2<1><<<dim3(HH / BN2, B_TOK / BM), 256, SMEM2_BYTES>>>(
        cb_hi, cb_lo, m1_hi, m1_lo, m1_b, nullptr, nullptr, h1_hi, h1_lo, HH, PP);
    mm_gemm2<0><<<dim3(HH / BN2, B_TOK / BM), 256, SMEM2_BYTES>>>(
        h1_hi, h1_lo, m2_hi, m2_lo, m2_b, nullptr, h232, nullptr, nullptr, HH, HH);
    // head
    head2_k<<<B_TOK / 32, 928>>>(h232, head_w, head_b, out);
}

// round 14
// speedup vs baseline: 1.0028x; 1.0028x over previous
#include <cuda_runtime.h>
#include <cuda_bf16.h>
#include <math.h>
#include <stdint.h>

// ---------------- problem constants ----------------
#define B_TOK 4096
#define DIN   512
#define PP    1024
#define HH    2048
#define EE    8
#define HSH   4096
#define OUTN  29
#define CAP   4096

// ---------------- big GEMM config (proven r8/r10/r11/r12) ----------------
#define BM 128
#define BN 256
#define BKC 32
#define ROWB 80
#define OFF_AH 0
#define OFF_AL (128 * ROWB)
#define OFF_BH (256 * ROWB)
#define OFF_BL (256 * ROWB + 256 * ROWB)
#define STAGE_BYTES (768 * ROWB)
#define NSTAGE 3
#define SMEM_BYTES (NSTAGE * STAGE_BYTES)
#define NTHR 512

// ---------------- PTX helpers ----------------
__device__ __forceinline__ uint32_t smem_u32(const void* p) {
    uint32_t a;
    asm("{ .reg .u64 t; cvta.to.shared.u64 t, %1; cvt.u32.u64 %0, t; }" : "=r"(a) : "l"(p));
    return a;
}
#define CP16(dst, src) asm volatile("cp.async.cg.shared.global [%0], [%1], 16;" :: "r"(dst), "l"(src) : "memory")
#define CP_COMMIT()    asm volatile("cp.async.commit_group;" ::: "memory")

#define LDSM4(r, addr) \
    asm volatile("ldmatrix.sync.aligned.m8n8.x4.shared.b16 {%0,%1,%2,%3}, [%4];" \
        : "=r"((r)[0]), "=r"((r)[1]), "=r"((r)[2]), "=r"((r)[3]) : "r"(addr))

#define MMA_BF16(c, a, b0, b1) \
    asm volatile("mma.sync.aligned.m16n8k16.row.col.f32.bf16.bf16.f32 " \
        "{%0,%1,%2,%3}, {%4,%5,%6,%7}, {%8,%9}, {%0,%1,%2,%3};" \
        : "+f"((c)[0]), "+f"((c)[1]), "+f"((c)[2]), "+f"((c)[3]) \
        : "r"((a)[0]), "r"((a)[1]), "r"((a)[2]), "r"((a)[3]), "r"(b0), "r"(b1))

// ---------------- scratch (device globals) ----------------
#define DEV __device__ __align__(128)
DEV __nv_bfloat16 g_x_hi [B_TOK * DIN],   g_x_lo [B_TOK * DIN];
DEV __nv_bfloat16 g_p_hi [B_TOK * PP],    g_p_lo [B_TOK * PP];
DEV float         g_p32  [B_TOK * PP];
DEV __nv_bfloat16 g_h_hi [(size_t)EE * CAP * HH], g_h_lo [(size_t)EE * CAP * HH];
DEV float         g_eo32 [(size_t)EE * CAP * PP];
DEV float         g_d32  [B_TOK * PP];
DEV __nv_bfloat16 g_su_hi[(size_t)B_TOK * HSH],   g_su_lo[(size_t)B_TOK * HSH];
DEV __nv_bfloat16 g_cb_hi[B_TOK * PP],    g_cb_lo[B_TOK * PP];
DEV __nv_bfloat16 g_h1_hi[B_TOK * HH],    g_h1_lo[B_TOK * HH];
DEV float         g_h232 [B_TOK * HH];
DEV __nv_bfloat16 g_wp_hi [PP * DIN],     g_wp_lo [PP * DIN];
DEV __nv_bfloat16 g_w1_hi [EE * HH * PP], g_w1_lo [EE * HH * PP];
DEV __nv_bfloat16 g_w2_hi [EE * PP * HH], g_w2_lo [EE * PP * HH];
DEV __nv_bfloat16 g_guw_hi[(size_t)2 * HSH * PP], g_guw_lo[(size_t)2 * HSH * PP];
DEV float         g_gub   [2 * HSH];
DEV __nv_bfloat16 g_sdw_hi[PP * HSH],     g_sdw_lo[PP * HSH];
DEV __nv_bfloat16 g_m1_hi [HH * PP],      g_m1_lo [HH * PP];
DEV __nv_bfloat16 g_m2_hi [HH * HH],      g_m2_lo [HH * HH];
DEV int   g_counts[EE];
DEV int   g_slot_token[EE * CAP];
DEV int   g_pair_slot[B_TOK * 2];
DEV float g_pair_gate[B_TOK * 2];

__device__ __forceinline__ float silu_f(float x) { return x / (1.0f + expf(-x)); }

// ---------------- stage fill (512 threads): A 128 rows + B 256 rows, hi+lo ----------------
template<bool GATHER>
__device__ __forceinline__ void fill_stage(uint32_t st, int tid,
    const char* Ah, const char* Al, const char* Bh, const char* Bl,
    size_t Kb, long rowA0, long rowB0, const int* __restrict__ tokRow, size_t kByte)
{
    {
        int row = tid >> 2, ch = tid & 3;
        uint32_t d = st + row * ROWB + ch * 16;
        long arow = GATHER ? (long)tokRow[row] : (rowA0 + row);
        size_t s = (size_t)arow * Kb + kByte + ch * 16;
        CP16(d + OFF_AH, Ah + s);
        CP16(d + OFF_AL, Al + s);
    }
#pragma unroll
    for (int i = 0; i < 2; i++) {
        int p = tid + (i << 9);
        int row = p >> 2, ch = p & 3;
        uint32_t d = st + row * ROWB + ch * 16;
        size_t s = (size_t)(rowB0 + row) * Kb + kByte + ch * 16;
        CP16(d + OFF_BH, Bh + s);
        CP16(d + OFF_BL, Bl + s);
    }
    CP_COMMIT();
}

// ---------------- bf16-split x3 GEMM, 16 warps, warp tile 32x64 ----------------
// MODE: 0=+bias 1=silu(+bias) 3=(+bias)+extra 4=fused SwiGLU pairs
template<int MODE, bool GATHER>
__global__ __launch_bounds__(NTHR, 1)
void mm_gemm(const __nv_bfloat16* __restrict__ Ahi, const __nv_bfloat16* __restrict__ Alo,
             const __nv_bfloat16* __restrict__ Bhi, const __nv_bfloat16* __restrict__ Blo,
             const float* __restrict__ bias, const float* __restrict__ extra,
             float* __restrict__ C32, __nv_bfloat16* __restrict__ Chi,
             __nv_bfloat16* __restrict__ Clo,
             const int* __restrict__ counts, const int* __restrict__ stok,
             int capRows, int N, int K)
{
    const int z  = blockIdx.z;
    const int m0 = blockIdx.y * BM;
    const int n0 = blockIdx.x * BN;
    int cnt = capRows;
    if (counts) { cnt = counts[z]; if (m0 >= cnt) return; }

    extern __shared__ __align__(128) char smem[];
    const uint32_t sb = smem_u32(smem);
    const int tid = threadIdx.x, lane = tid & 31, wid = tid >> 5;
    const int warp_m = wid & 3;
    const int warp_n = wid >> 2;

    const size_t Kb = (size_t)K * 2;
    const long rowA0 = (long)z * capRows + m0;
    const long rowB0 = (long)z * N + n0;
    const int* tokRow = GATHER ? (stok + z * CAP + m0) : nullptr;
    const int  C = K / BKC;

    float acc[2][8][4];
#pragma unroll
    for (int i = 0; i < 2; i++)
#pragma unroll
        for (int j = 0; j < 8; j++)
#pragma unroll
            for (int q = 0; q < 4; q++) acc[i][j][q] = 0.f;

    const char* Ah = (const char*)Ahi; const char* Al = (const char*)Alo;
    const char* Bh = (const char*)Bhi; const char* Bl = (const char*)Blo;

    fill_stage<GATHER>(sb, tid, Ah, Al, Bh, Bl, Kb, rowA0, rowB0, tokRow, 0);
    if (C > 1) fill_stage<GATHER>(sb + STAGE_BYTES, tid, Ah, Al, Bh, Bl, Kb, rowA0, rowB0, tokRow, 64);

    const int lm = lane & 15;
    const int lkb = (lane >> 4) << 4;

    for (int c = 0; c < C; c++) {
        if (c + 2 < C) asm volatile("cp.async.wait_group 1;" ::: "memory");
        else           asm volatile("cp.async.wait_group 0;" ::: "memory");
        __syncthreads();
        if (c + 2 < C)
            fill_stage<GATHER>(sb + ((c + 2) % NSTAGE) * STAGE_BYTES, tid, Ah, Al, Bh, Bl,
                               Kb, rowA0, rowB0, tokRow, (size_t)(c + 2) * 64);

        const uint32_t stg = sb + (c % NSTAGE) * STAGE_BYTES;
#pragma unroll
        for (int kk = 0; kk < 2; kk++) {
            const uint32_t kb = kk * 32 + lkb;
            uint32_t a_h[2][4], a_l[2][4];
#pragma unroll
            for (int mt = 0; mt < 2; mt++) {
                uint32_t ad = stg + (warp_m * 32 + mt * 16 + lm) * ROWB + kb;
                LDSM4(a_h[mt], ad + OFF_AH);
                LDSM4(a_l[mt], ad + OFF_AL);
            }
#pragma unroll
            for (int n2 = 0; n2 < 4; n2++) {
                uint32_t b_h[4], b_l[4];
                uint32_t bd = stg + (warp_n * 64 + n2 * 16 + lm) * ROWB + kb;
                LDSM4(b_h, bd + OFF_BH);
                LDSM4(b_l, bd + OFF_BL);
#pragma unroll
                for (int mt = 0; mt < 2; mt++)
#pragma unroll
                    for (int o = 0; o < 2; o++) {
                        const int nt = n2 * 2 + o;
                        MMA_BF16(acc[mt][nt], a_h[mt], b_h[o], b_h[o + 2]);
                        MMA_BF16(acc[mt][nt], a_h[mt], b_l[o], b_l[o + 2]);
                        MMA_BF16(acc[mt][nt], a_l[mt], b_h[o], b_h[o + 2]);
                    }
            }
        }
    }

    const float* biasz = bias + (size_t)z * N;
#pragma unroll
    for (int mt = 0; mt < 2; mt++) {
#pragma unroll
        for (int half = 0; half < 2; half++) {
            const int rtile = warp_m * 32 + mt * 16 + (lane >> 2) + half * 8;
            if (m0 + rtile >= cnt) continue;
            const size_t gr = (size_t)z * capRows + m0 + rtile;
#pragma unroll
            for (int nt = 0; nt < 8; nt++) {
                const int col = n0 + warp_n * 64 + nt * 8 + (lane & 3) * 2;
                float v0 = acc[mt][nt][half * 2 + 0] + biasz[col];
                float v1 = acc[mt][nt][half * 2 + 1] + biasz[col + 1];
                if (MODE == 4) {
                    float w = silu_f(v0) * v1;
                    __nv_bfloat16 h = __float2bfloat16(w);
                    const size_t o = gr * (size_t)(N >> 1) + (col >> 1);
                    Chi[o] = h;
                    Clo[o] = __float2bfloat16(w - __bfloat162float(h));
                    continue;
                }
                if (MODE == 1) { v0 = silu_f(v0); v1 = silu_f(v1); }
                if (MODE == 3) {
                    const float2 e = *(const float2*)&extra[gr * N + col];
                    v0 += e.x; v1 += e.y;
                }
                if (C32) { float2 w = {v0, v1}; *(float2*)&C32[gr * N + col] = w; }
                if (Chi) {
                    __nv_bfloat16 h0 = __float2bfloat16(v0);
                    __nv_bfloat16 h1 = __float2bfloat16(v1);
                    __nv_bfloat162 hp; hp.x = h0; hp.y = h1;
                    *(__nv_bfloat162*)&Chi[gr * N + col] = hp;
                    __nv_bfloat162 lp;
                    lp.x = __float2bfloat16(v0 - __bfloat162float(h0));
                    lp.y = __float2bfloat16(v1 - __bfloat162float(h1));
                    *(__nv_bfloat162*)&Clo[gr * N + col] = lp;
                }
            }
        }
    }
}

// ---------------- small kernels ----------------
__global__ void conv_split_k(const float* __restrict__ in, __nv_bfloat16* __restrict__ hi,
                             __nv_bfloat16* __restrict__ lo, size_t n)
{
    size_t i = (size_t)blockIdx.x * blockDim.x + threadIdx.x;
    if (i >= n) return;
    float v = in[i];
    __nv_bfloat16 h = __float2bfloat16(v);
    hi[i] = h;
    lo[i] = __float2bfloat16(v - __bfloat162float(h));
}

template<int RMUL>
__global__ __launch_bounds__(256)
void convT2_k(const float* __restrict__ W, __nv_bfloat16* __restrict__ hi,
              __nv_bfloat16* __restrict__ lo, int K, int N, int radd)
{
    __shared__ float t[32][129];
    const int k0 = blockIdx.y * 32, n0 = blockIdx.x * 128;
    const float* Wz = W + (size_t)blockIdx.z * K * N;
    const int tid = threadIdx.x;
    {
        const int c = tid & 127;
        for (int r = tid >> 7; r < 32; r += 2)
            t[r][c] = Wz[(size_t)(k0 + r) * N + n0 + c];
    }
    __syncthreads();
    const size_t zbase = (size_t)blockIdx.z * N * RMUL;
    for (int idx = tid; idx < 128 * 16; idx += 256) {
        const int n = idx >> 4, kp = idx & 15;
        float v0 = t[kp * 2][n], v1 = t[kp * 2 + 1][n];
        __nv_bfloat16 h0 = __float2bfloat16(v0), h1 = __float2bfloat16(v1);
        __nv_bfloat162 hp; hp.x = h0; hp.y = h1;
        __nv_bfloat162 lp;
        lp.x = __float2bfloat16(v0 - __bfloat162float(h0));
        lp.y = __float2bfloat16(v1 - __bfloat162float(h1));
        const size_t orow = zbase + (size_t)(n0 + n) * RMUL + radd;
        const size_t o = orow * K + k0 + kp * 2;
        *(__nv_bfloat162*)&hi[o] = hp;
        *(__nv_bfloat162*)&lo[o] = lp;
    }
}

__global__ void ileave_bias_k(const float* __restrict__ a, const float* __restrict__ b,
                              float* __restrict__ o, int n)
{
    int i = blockIdx.x * 256 + threadIdx.x;
    if (i < n) { o[2 * i] = a[i]; o[2 * i + 1] = b[i]; }
}

__global__ void zero_counts_k(int* counts) { if (threadIdx.x < EE) counts[threadIdx.x] = 0; }

__global__ void router_k(const float* __restrict__ p, const float* __restrict__ Wg,
                         int* __restrict__ counts, int* __restrict__ slot_token,
                         int* __restrict__ pair_slot, float* __restrict__ pair_gate)
{
    const int t = blockIdx.x;
    const int tid = threadIdx.x; // 128
    __shared__ float red[EE][128];
    float acc[EE];
#pragma unroll
    for (int e = 0; e < EE; e++) acc[e] = 0.f;
    const float* pr = p + (size_t)t * PP;
    for (int j = tid; j < PP; j += 128) {
        float pv = pr[j];
        const float* wg = Wg + (size_t)j * EE;
#pragma unroll
        for (int e = 0; e < EE; e++) acc[e] += pv * wg[e];
    }
#pragma unroll
    for (int e = 0; e < EE; e++) red[e][tid] = acc[e];
    __syncthreads();
    if (tid == 0) {
        float logit[EE];
        for (int e = 0; e < EE; e++) {
            float s = 0.f;
            for (int i = 0; i < 128; i++) s += red[e][i];
            logit[e] = s;
        }
        int i0 = 0;
        for (int e = 1; e < EE; e++) if (logit[e] > logit[i0]) i0 = e;
        int i1 = (i0 == 0) ? 1 : 0;
        for (int e = 0; e < EE; e++) {
            if (e == i0) continue;
            if (logit[e] > logit[i1]) i1 = e;
        }
        float g0 = 1.f / (1.f + expf(logit[i1] - logit[i0]));
        float g1 = 1.f - g0;
        int s0 = atomicAdd(&counts[i0], 1);
        int s1 = atomicAdd(&counts[i1], 1);
        slot_token[i0 * CAP + s0] = t;
        slot_token[i1 * CAP + s1] = t;
        pair_slot[2 * t]     = i0 * CAP + s0;
        pair_slot[2 * t + 1] = i1 * CAP + s1;
        pair_gate[2 * t]     = g0;
        pair_gate[2 * t + 1] = g1;
    }
}

// fused: cb = split(d32 + g0*eo[s0] + g1*eo[s1])   (combine + residual + split)
__global__ void addsplit_k(const float* __restrict__ d32, const float* __restrict__ eo,
                           const int* __restrict__ pair_slot, const float* __restrict__ pair_gate,
                           __nv_bfloat16* __restrict__ cb_hi, __nv_bfloat16* __restrict__ cb_lo)
{
    int idx = blockIdx.x * blockDim.x + threadIdx.x;
    if (idx >= B_TOK * PP) return;
    int t = idx >> 10, j = idx & (PP - 1);
    int s0 = pair_slot[2 * t], s1 = pair_slot[2 * t + 1];
    float g0 = pair_gate[2 * t], g1 = pair_gate[2 * t + 1];
    float moe = g0 * eo[(size_t)s0 * PP + j] + g1 * eo[(size_t)s1 * PP + j];
    float v = d32[idx] + moe;
    __nv_bfloat16 h = __float2bfloat16(v);
    cb_hi[idx] = h;
    cb_lo[idx] = __float2bfloat16(v - __bfloat162float(h));
}

// ---------------- head: tiled, 32 tokens per block ----------------
#define HKC 128
__global__ __launch_bounds__(928)
void head2_k(const float* __restrict__ hid2, const float* __restrict__ head_w,
             const float* __restrict__ head_b, float* __restrict__ out)
{
    __shared__ float hs[32 * HKC];
    __shared__ float ws[HKC * 30];
    const int tid = threadIdx.x;
    const int tok0 = blockIdx.x * 32;
    const int tokl = tid / OUTN;
    const int o    = tid % OUTN;
    float acc = 0.f;

    for (int kc = 0; kc < HH; kc += HKC) {
        for (int i = tid; i < 32 * HKC; i += 928)
            hs[i] = hid2[(size_t)(tok0 + (i >> 7)) * HH + kc + (i & (HKC - 1))];
        for (int i = tid; i < HKC * OUTN; i += 928) {
            int k = i / OUTN, oo = i % OUTN;
            ws[k * 30 + oo] = head_w[(size_t)(kc + k) * OUTN + oo];
        }
        __syncthreads();
        const float* hrow = hs + tokl * HKC;
#pragma unroll 4
        for (int k = 0; k < HKC; k++)
            acc += hrow[k] * ws[k * 30 + o];
        __syncthreads();
    }
    out[(size_t)(tok0 + tokl) * OUTN + o] = acc + head_b[o];
}

// ---------------- launch ----------------
template <typename T>
static T* symaddr(const void* sym) { void* p = nullptr; cudaGetSymbolAddress(&p, sym); return (T*)p; }

extern "C" void kernel_launch(void* const* d_in, const int* in_sizes, int n_in,
                              void* d_out, int out_size)
{
    const float* x      = (const float*)d_in[0];
    const float* Wproj  = (const float*)d_in[1];
    const float* bproj  = (const float*)d_in[2];
    const float* Wg     = (const float*)d_in[3];
    const float* W1     = (const float*)d_in[4];
    const float* b1     = (const float*)d_in[5];
    const float* W2     = (const float*)d_in[6];
    const float* b2     = (const float*)d_in[7];
    const float* sg_w   = (const float*)d_in[8];
    const float* sg_b   = (const float*)d_in[9];
    const float* su_w   = (const float*)d_in[10];
    const float* su_b   = (const float*)d_in[11];
    const float* sd_w   = (const float*)d_in[12];
    const float* sd_b   = (const float*)d_in[13];
    const float* m1_w   = (const float*)d_in[14];
    const float* m1_b   = (const float*)d_in[15];
    const float* m2_w   = (const float*)d_in[16];
    const float* m2_b   = (const float*)d_in[17];
    const float* head_w = (const float*)d_in[18];
    const float* head_b = (const float*)d_in[19];
    float* out = (float*)d_out;

    static cudaStream_t s1 = nullptr;
    static cudaEvent_t evFork, evP, evW1, evW2, evSw;
    if (!s1) {
        cudaStreamCreateWithFlags(&s1, cudaStreamNonBlocking);
        cudaEventCreateWithFlags(&evFork, cudaEventDisableTiming);
        cudaEventCreateWithFlags(&evP,    cudaEventDisableTiming);
        cudaEventCreateWithFlags(&evW1,   cudaEventDisableTiming);
        cudaEventCreateWithFlags(&evW2,   cudaEventDisableTiming);
        cudaEventCreateWithFlags(&evSw,   cudaEventDisableTiming);
        cudaFuncSetAttribute(mm_gemm<0, false>, cudaFuncAttributeMaxDynamicSharedMemorySize, SMEM_BYTES);
        cudaFuncSetAttribute(mm_gemm<1, false>, cudaFuncAttributeMaxDynamicSharedMemorySize, SMEM_BYTES);
        cudaFuncSetAttribute(mm_gemm<4, false>, cudaFuncAttributeMaxDynamicSharedMemorySize, SMEM_BYTES);
        cudaFuncSetAttribute(mm_gemm<1, true>,  cudaFuncAttributeMaxDynamicSharedMemorySize, SMEM_BYTES);
    }

    __nv_bfloat16 *x_hi = symaddr<__nv_bfloat16>(g_x_hi),  *x_lo = symaddr<__nv_bfloat16>(g_x_lo);
    __nv_bfloat16 *p_hi = symaddr<__nv_bfloat16>(g_p_hi),  *p_lo = symaddr<__nv_bfloat16>(g_p_lo);
    float *p32  = symaddr<float>(g_p32);
    __nv_bfloat16 *h_hi  = symaddr<__nv_bfloat16>(g_h_hi),  *h_lo  = symaddr<__nv_bfloat16>(g_h_lo);
    float *eo32 = symaddr<float>(g_eo32);
    float *d32  = symaddr<float>(g_d32);
    __nv_bfloat16 *su_hi = symaddr<__nv_bfloat16>(g_su_hi), *su_lo = symaddr<__nv_bfloat16>(g_su_lo);
    __nv_bfloat16 *cb_hi = symaddr<__nv_bfloat16>(g_cb_hi), *cb_lo = symaddr<__nv_bfloat16>(g_cb_lo);
    __nv_bfloat16 *h1_hi = symaddr<__nv_bfloat16>(g_h1_hi), *h1_lo = symaddr<__nv_bfloat16>(g_h1_lo);
    float *h232 = symaddr<float>(g_h232);
    __nv_bfloat16 *wp_hi = symaddr<__nv_bfloat16>(g_wp_hi), *wp_lo = symaddr<__nv_bfloat16>(g_wp_lo);
    __nv_bfloat16 *w1_hi = symaddr<__nv_bfloat16>(g_w1_hi), *w1_lo = symaddr<__nv_bfloat16>(g_w1_lo);
    __nv_bfloat16 *w2_hi = symaddr<__nv_bfloat16>(g_w2_hi), *w2_lo = symaddr<__nv_bfloat16>(g_w2_lo);
    __nv_bfloat16 *guw_hi = symaddr<__nv_bfloat16>(g_guw_hi), *guw_lo = symaddr<__nv_bfloat16>(g_guw_lo);
    float *gub = symaddr<float>(g_gub);
    __nv_bfloat16 *sdw_hi = symaddr<__nv_bfloat16>(g_sdw_hi), *sdw_lo = symaddr<__nv_bfloat16>(g_sdw_lo);
    __nv_bfloat16 *m1_hi = symaddr<__nv_bfloat16>(g_m1_hi), *m1_lo = symaddr<__nv_bfloat16>(g_m1_lo);
    __nv_bfloat16 *m2_hi = symaddr<__nv_bfloat16>(g_m2_hi), *m2_lo = symaddr<__nv_bfloat16>(g_m2_lo);
    int *counts = symaddr<int>(g_counts);
    int *stok   = symaddr<int>(g_slot_token);
    int *pslot  = symaddr<int>(g_pair_slot);
    float *pgate = symaddr<float>(g_pair_gate);

    // ---- fork side stream ----
    cudaEventRecord(evFork, 0);
    cudaStreamWaitEvent(s1, evFork, 0);

    // s1: heavy weight transposes (overlap proj GEMM + router)
    convT2_k<1><<<dim3(HH / 128, PP / 32, EE),  256, 0, s1>>>(W1, w1_hi, w1_lo, PP, HH, 0);
    cudaEventRecord(evW1, s1);
    convT2_k<1><<<dim3(PP / 128, HH / 32, EE),  256, 0, s1>>>(W2, w2_hi, w2_lo, HH, PP, 0);
    cudaEventRecord(evW2, s1);
    convT2_k<2><<<dim3(HSH / 128, PP / 32, 1),  256, 0, s1>>>(sg_w, guw_hi, guw_lo, PP, HSH, 0);
    convT2_k<2><<<dim3(HSH / 128, PP / 32, 1),  256, 0, s1>>>(su_w, guw_hi, guw_lo, PP, HSH, 1);
    ileave_bias_k<<<(HSH + 255) / 256, 256, 0, s1>>>(sg_b, su_b, gub, HSH);
    convT2_k<1><<<dim3(PP / 128, HSH / 32, 1),  256, 0, s1>>>(sd_w, sdw_hi, sdw_lo, HSH, PP, 0);
    convT2_k<1><<<dim3(HH / 128, PP / 32, 1),   256, 0, s1>>>(m1_w, m1_hi, m1_lo, PP, HH, 0);
    convT2_k<1><<<dim3(HH / 128, HH / 32, 1),   256, 0, s1>>>(m2_w, m2_hi, m2_lo, HH, HH, 0);

    // main: input split + proj GEMM + router
    conv_split_k<<<(B_TOK * DIN + 255) / 256, 256>>>(x, x_hi, x_lo, (size_t)B_TOK * DIN);
    convT2_k<1><<<dim3(PP / 128, DIN / 32, 1),  256>>>(Wproj, wp_hi, wp_lo, DIN, PP, 0);
    mm_gemm<0, false><<<dim3(PP / BN, B_TOK / BM, 1), NTHR, SMEM_BYTES>>>(
        x_hi, x_lo, wp_hi, wp_lo, bproj, nullptr, p32, p_hi, p_lo,
        nullptr, nullptr, B_TOK, PP, DIN);
    cudaEventRecord(evP, 0);
    zero_counts_k<<<1, 32>>>(counts);
    router_k<<<B_TOK, 128>>>(p32, Wg, counts, stok, pslot, pgate);

    // s1: fused shared SwiGLU, then down-proj partial d32 = su@sdw + sd_b
    // (both overlap the expert chain on the main stream)
    cudaStreamWaitEvent(s1, evP, 0);
    mm_gemm<4, false><<<dim3((2 * HSH) / BN, B_TOK / BM, 1), NTHR, SMEM_BYTES, s1>>>(
        p_hi, p_lo, guw_hi, guw_lo, gub, nullptr, nullptr, su_hi, su_lo,
        nullptr, nullptr, B_TOK, 2 * HSH, PP);
    mm_gemm<0, false><<<dim3(PP / BN, B_TOK / BM, 1), NTHR, SMEM_BYTES, s1>>>(
        su_hi, su_lo, sdw_hi, sdw_lo, sd_b, nullptr, d32, nullptr, nullptr,
        nullptr, nullptr, B_TOK, PP, HSH);
    cudaEventRecord(evSw, s1);

    // main: expert chain
    cudaStreamWaitEvent(0, evW1, 0);
    mm_gemm<1, true><<<dim3(HH / BN, CAP / BM, EE), NTHR, SMEM_BYTES>>>(
        p_hi, p_lo, w1_hi, w1_lo, b1, nullptr, nullptr, h_hi, h_lo,
        counts, stok, CAP, HH, PP);
    cudaStreamWaitEvent(0, evW2, 0);
    mm_gemm<0, false><<<dim3(PP / BN, CAP / BM, EE), NTHR, SMEM_BYTES>>>(
        h_hi, h_lo, w2_hi, w2_lo, b2, nullptr, eo32, nullptr, nullptr,
        counts, nullptr, CAP, PP, HH);

    // join: cb = split(d32 + combine(eo))
    cudaStreamWaitEvent(0, evSw, 0);
    addsplit_k<<<(B_TOK * PP + 255) / 256, 256>>>(d32, eo32, pslot, pgate, cb_hi, cb_lo);

    // output MLP (big-tile config, r12-proven)
    mm_gemm<1, false><<<dim3(HH / BN, B_TOK / BM, 1), NTHR, SMEM_BYTES>>>(
        cb_hi, cb_lo, m1_hi, m1_lo, m1_b, nullptr, nullptr, h1_hi, h1_lo,
        nullptr, nullptr, B_TOK, HH, PP);
    mm_gemm<0, false><<<dim3(HH / BN, B_TOK / BM, 1), NTHR, SMEM_BYTES>>>(
        h1_hi, h1_lo, m2_hi, m2_lo, m2_b, nullptr, h232, nullptr, nullptr,
        nullptr, nullptr, B_TOK, HH, HH);
    // head
    head2_k<<<B_TOK / 32, 928>>>(h232, head_w, head_b, out);
}

// round 15
// speedup vs baseline: 1.0104x; 1.0076x over previous
#include <cuda_runtime.h>
#include <cuda_bf16.h>
#include <math.h>
#include <stdint.h>

// ---------------- problem constants ----------------
#define B_TOK 4096
#define DIN   512
#define PP    1024
#define HH    2048
#define EE    8
#define HSH   4096
#define OUTN  29
#define CAP   4096

// ---------------- big GEMM config (proven r8/r10/r11/r12) ----------------
#define BM 128
#define BN 256
#define BKC 32
#define ROWB 80
#define OFF_AH 0
#define OFF_AL (128 * ROWB)
#define OFF_BH (256 * ROWB)
#define OFF_BL (256 * ROWB + 256 * ROWB)
#define STAGE_BYTES (768 * ROWB)
#define NSTAGE 3
#define SMEM_BYTES (NSTAGE * STAGE_BYTES)
#define NTHR 512

// ---------------- PTX helpers ----------------
__device__ __forceinline__ uint32_t smem_u32(const void* p) {
    uint32_t a;
    asm("{ .reg .u64 t; cvta.to.shared.u64 t, %1; cvt.u32.u64 %0, t; }" : "=r"(a) : "l"(p));
    return a;
}
#define CP16(dst, src) asm volatile("cp.async.cg.shared.global [%0], [%1], 16;" :: "r"(dst), "l"(src) : "memory")
#define CP_COMMIT()    asm volatile("cp.async.commit_group;" ::: "memory")

#define LDSM4(r, addr) \
    asm volatile("ldmatrix.sync.aligned.m8n8.x4.shared.b16 {%0,%1,%2,%3}, [%4];" \
        : "=r"((r)[0]), "=r"((r)[1]), "=r"((r)[2]), "=r"((r)[3]) : "r"(addr))

#define MMA_BF16(c, a, b0, b1) \
    asm volatile("mma.sync.aligned.m16n8k16.row.col.f32.bf16.bf16.f32 " \
        "{%0,%1,%2,%3}, {%4,%5,%6,%7}, {%8,%9}, {%0,%1,%2,%3};" \
        : "+f"((c)[0]), "+f"((c)[1]), "+f"((c)[2]), "+f"((c)[3]) \
        : "r"((a)[0]), "r"((a)[1]), "r"((a)[2]), "r"((a)[3]), "r"(b0), "r"(b1))

// ---------------- scratch (device globals) ----------------
#define DEV __device__ __align__(128)
DEV __nv_bfloat16 g_x_hi [B_TOK * DIN],   g_x_lo [B_TOK * DIN];
DEV __nv_bfloat16 g_p_hi [B_TOK * PP],    g_p_lo [B_TOK * PP];
DEV float         g_p32  [B_TOK * PP];
DEV __nv_bfloat16 g_h_hi [(size_t)EE * CAP * HH], g_h_lo [(size_t)EE * CAP * HH];
DEV float         g_eo32 [(size_t)EE * CAP * PP];
DEV __nv_bfloat16 g_su_hi[(size_t)B_TOK * HSH],   g_su_lo[(size_t)B_TOK * HSH];
DEV __nv_bfloat16 g_cb_hi[B_TOK * PP],    g_cb_lo[B_TOK * PP];
DEV __nv_bfloat16 g_h1_hi[B_TOK * HH],    g_h1_lo[B_TOK * HH];
DEV float         g_h232 [B_TOK * HH];
DEV __nv_bfloat16 g_wp_hi [PP * DIN],     g_wp_lo [PP * DIN];
DEV __nv_bfloat16 g_w1_hi [EE * HH * PP], g_w1_lo [EE * HH * PP];
DEV __nv_bfloat16 g_w2_hi [EE * PP * HH], g_w2_lo [EE * PP * HH];
DEV __nv_bfloat16 g_guw_hi[(size_t)2 * HSH * PP], g_guw_lo[(size_t)2 * HSH * PP];
DEV float         g_gub   [2 * HSH];
DEV __nv_bfloat16 g_sdw_hi[PP * HSH],     g_sdw_lo[PP * HSH];
DEV __nv_bfloat16 g_m1_hi [HH * PP],      g_m1_lo [HH * PP];
DEV __nv_bfloat16 g_m2_hi [HH * HH],      g_m2_lo [HH * HH];
DEV int   g_counts[EE];
DEV int   g_slot_token[EE * CAP];
DEV int   g_pair_slot[B_TOK * 2];
DEV float g_pair_gate[B_TOK * 2];

__device__ __forceinline__ float silu_f(float x) { return x / (1.0f + expf(-x)); }

// ---------------- stage fill (512 threads): A 128 rows + B 256 rows, hi+lo ----------------
template<bool GATHER>
__device__ __forceinline__ void fill_stage(uint32_t st, int tid,
    const char* Ah, const char* Al, const char* Bh, const char* Bl,
    size_t Kb, long rowA0, long rowB0, const int* __restrict__ tokRow, size_t kByte)
{
    {
        int row = tid >> 2, ch = tid & 3;
        uint32_t d = st + row * ROWB + ch * 16;
        long arow = GATHER ? (long)tokRow[row] : (rowA0 + row);
        size_t s = (size_t)arow * Kb + kByte + ch * 16;
        CP16(d + OFF_AH, Ah + s);
        CP16(d + OFF_AL, Al + s);
    }
#pragma unroll
    for (int i = 0; i < 2; i++) {
        int p = tid + (i << 9);
        int row = p >> 2, ch = p & 3;
        uint32_t d = st + row * ROWB + ch * 16;
        size_t s = (size_t)(rowB0 + row) * Kb + kByte + ch * 16;
        CP16(d + OFF_BH, Bh + s);
        CP16(d + OFF_BL, Bl + s);
    }
    CP_COMMIT();
}

// ---------------- bf16-split x3 GEMM, 16 warps, warp tile 32x64 ----------------
// MODE: 0=+bias 1=silu(+bias) 3=(+bias)+extra 4=fused SwiGLU pairs
// MODE 5: (+bias) + g0*eo[s0,col] + g1*eo[s1,col]   (fused MoE combine, extra=eo32)
template<int MODE, bool GATHER>
__global__ __launch_bounds__(NTHR, 1)
void mm_gemm(const __nv_bfloat16* __restrict__ Ahi, const __nv_bfloat16* __restrict__ Alo,
             const __nv_bfloat16* __restrict__ Bhi, const __nv_bfloat16* __restrict__ Blo,
             const float* __restrict__ bias, const float* __restrict__ extra,
             float* __restrict__ C32, __nv_bfloat16* __restrict__ Chi,
             __nv_bfloat16* __restrict__ Clo,
             const int* __restrict__ counts, const int* __restrict__ stok,
             const int* __restrict__ pslot, const float* __restrict__ pgate,
             int capRows, int N, int K)
{
    const int z  = blockIdx.z;
    const int m0 = blockIdx.y * BM;
    const int n0 = blockIdx.x * BN;
    int cnt = capRows;
    if (counts) { cnt = counts[z]; if (m0 >= cnt) return; }

    extern __shared__ __align__(128) char smem[];
    const uint32_t sb = smem_u32(smem);
    const int tid = threadIdx.x, lane = tid & 31, wid = tid >> 5;
    const int warp_m = wid & 3;
    const int warp_n = wid >> 2;

    const size_t Kb = (size_t)K * 2;
    const long rowA0 = (long)z * capRows + m0;
    const long rowB0 = (long)z * N + n0;
    const int* tokRow = GATHER ? (stok + z * CAP + m0) : nullptr;
    const int  C = K / BKC;

    float acc[2][8][4];
#pragma unroll
    for (int i = 0; i < 2; i++)
#pragma unroll
        for (int j = 0; j < 8; j++)
#pragma unroll
            for (int q = 0; q < 4; q++) acc[i][j][q] = 0.f;

    const char* Ah = (const char*)Ahi; const char* Al = (const char*)Alo;
    const char* Bh = (const char*)Bhi; const char* Bl = (const char*)Blo;

    fill_stage<GATHER>(sb, tid, Ah, Al, Bh, Bl, Kb, rowA0, rowB0, tokRow, 0);
    if (C > 1) fill_stage<GATHER>(sb + STAGE_BYTES, tid, Ah, Al, Bh, Bl, Kb, rowA0, rowB0, tokRow, 64);

    const int lm = lane & 15;
    const int lkb = (lane >> 4) << 4;

    for (int c = 0; c < C; c++) {
        if (c + 2 < C) asm volatile("cp.async.wait_group 1;" ::: "memory");
        else           asm volatile("cp.async.wait_group 0;" ::: "memory");
        __syncthreads();
        if (c + 2 < C)
            fill_stage<GATHER>(sb + ((c + 2) % NSTAGE) * STAGE_BYTES, tid, Ah, Al, Bh, Bl,
                               Kb, rowA0, rowB0, tokRow, (size_t)(c + 2) * 64);

        const uint32_t stg = sb + (c % NSTAGE) * STAGE_BYTES;
#pragma unroll
        for (int kk = 0; kk < 2; kk++) {
            const uint32_t kb = kk * 32 + lkb;
            uint32_t a_h[2][4], a_l[2][4];
#pragma unroll
            for (int mt = 0; mt < 2; mt++) {
                uint32_t ad = stg + (warp_m * 32 + mt * 16 + lm) * ROWB + kb;
                LDSM4(a_h[mt], ad + OFF_AH);
                LDSM4(a_l[mt], ad + OFF_AL);
            }
#pragma unroll
            for (int n2 = 0; n2 < 4; n2++) {
                uint32_t b_h[4], b_l[4];
                uint32_t bd = stg + (warp_n * 64 + n2 * 16 + lm) * ROWB + kb;
                LDSM4(b_h, bd + OFF_BH);
                LDSM4(b_l, bd + OFF_BL);
#pragma unroll
                for (int mt = 0; mt < 2; mt++)
#pragma unroll
                    for (int o = 0; o < 2; o++) {
                        const int nt = n2 * 2 + o;
                        MMA_BF16(acc[mt][nt], a_h[mt], b_h[o], b_h[o + 2]);
                        MMA_BF16(acc[mt][nt], a_h[mt], b_l[o], b_l[o + 2]);
                        MMA_BF16(acc[mt][nt], a_l[mt], b_h[o], b_h[o + 2]);
                    }
            }
        }
    }

    const float* biasz = bias + (size_t)z * N;
#pragma unroll
    for (int mt = 0; mt < 2; mt++) {
#pragma unroll
        for (int half = 0; half < 2; half++) {
            const int rtile = warp_m * 32 + mt * 16 + (lane >> 2) + half * 8;
            if (m0 + rtile >= cnt) continue;
            const size_t gr = (size_t)z * capRows + m0 + rtile;
            // MODE 5: per-row MoE gather metadata
            long e0base = 0, e1base = 0;
            float mg0 = 0.f, mg1 = 0.f;
            if (MODE == 5) {
                const int s0 = pslot[2 * gr], s1p = pslot[2 * gr + 1];
                mg0 = pgate[2 * gr]; mg1 = pgate[2 * gr + 1];
                e0base = (long)s0 * PP;
                e1base = (long)s1p * PP;
            }
#pragma unroll
            for (int nt = 0; nt < 8; nt++) {
                const int col = n0 + warp_n * 64 + nt * 8 + (lane & 3) * 2;
                float v0 = acc[mt][nt][half * 2 + 0] + biasz[col];
                float v1 = acc[mt][nt][half * 2 + 1] + biasz[col + 1];
                if (MODE == 4) {
                    float w = silu_f(v0) * v1;
                    __nv_bfloat16 h = __float2bfloat16(w);
                    const size_t o = gr * (size_t)(N >> 1) + (col >> 1);
                    Chi[o] = h;
                    Clo[o] = __float2bfloat16(w - __bfloat162float(h));
                    continue;
                }
                if (MODE == 1) { v0 = silu_f(v0); v1 = silu_f(v1); }
                if (MODE == 3) {
                    const float2 e = *(const float2*)&extra[gr * N + col];
                    v0 += e.x; v1 += e.y;
                }
                if (MODE == 5) {
                    const float2 e0 = *(const float2*)&extra[e0base + col];
                    const float2 e1 = *(const float2*)&extra[e1base + col];
                    float moe0 = mg0 * e0.x + mg1 * e1.x;
                    float moe1 = mg0 * e0.y + mg1 * e1.y;
                    v0 += moe0; v1 += moe1;
                }
                if (C32) { float2 w = {v0, v1}; *(float2*)&C32[gr * N + col] = w; }
                if (Chi) {
                    __nv_bfloat16 h0 = __float2bfloat16(v0);
                    __nv_bfloat16 h1 = __float2bfloat16(v1);
                    __nv_bfloat162 hp; hp.x = h0; hp.y = h1;
                    *(__nv_bfloat162*)&Chi[gr * N + col] = hp;
                    __nv_bfloat162 lp;
                    lp.x = __float2bfloat16(v0 - __bfloat162float(h0));
                    lp.y = __float2bfloat16(v1 - __bfloat162float(h1));
                    *(__nv_bfloat162*)&Clo[gr * N + col] = lp;
                }
            }
        }
    }
}

// ---------------- small kernels ----------------
__global__ void conv_split_k(const float* __restrict__ in, __nv_bfloat16* __restrict__ hi,
                             __nv_bfloat16* __restrict__ lo, size_t n)
{
    size_t i = (size_t)blockIdx.x * blockDim.x + threadIdx.x;
    if (i >= n) return;
    float v = in[i];
    __nv_bfloat16 h = __float2bfloat16(v);
    hi[i] = h;
    lo[i] = __float2bfloat16(v - __bfloat162float(h));
}

template<int RMUL>
__global__ __launch_bounds__(256)
void convT2_k(const float* __restrict__ W, __nv_bfloat16* __restrict__ hi,
              __nv_bfloat16* __restrict__ lo, int K, int N, int radd)
{
    __shared__ float t[32][129];
    const int k0 = blockIdx.y * 32, n0 = blockIdx.x * 128;
    const float* Wz = W + (size_t)blockIdx.z * K * N;
    const int tid = threadIdx.x;
    {
        const int c = tid & 127;
        for (int r = tid >> 7; r < 32; r += 2)
            t[r][c] = Wz[(size_t)(k0 + r) * N + n0 + c];
    }
    __syncthreads();
    const size_t zbase = (size_t)blockIdx.z * N * RMUL;
    for (int idx = tid; idx < 128 * 16; idx += 256) {
        const int n = idx >> 4, kp = idx & 15;
        float v0 = t[kp * 2][n], v1 = t[kp * 2 + 1][n];
        __nv_bfloat16 h0 = __float2bfloat16(v0), h1 = __float2bfloat16(v1);
        __nv_bfloat162 hp; hp.x = h0; hp.y = h1;
        __nv_bfloat162 lp;
        lp.x = __float2bfloat16(v0 - __bfloat162float(h0));
        lp.y = __float2bfloat16(v1 - __bfloat162float(h1));
        const size_t orow = zbase + (size_t)(n0 + n) * RMUL + radd;
        const size_t o = orow * K + k0 + kp * 2;
        *(__nv_bfloat162*)&hi[o] = hp;
        *(__nv_bfloat162*)&lo[o] = lp;
    }
}

__global__ void ileave_bias_k(const float* __restrict__ a, const float* __restrict__ b,
                              float* __restrict__ o, int n)
{
    int i = blockIdx.x * 256 + threadIdx.x;
    if (i < n) { o[2 * i] = a[i]; o[2 * i + 1] = b[i]; }
}

__global__ void zero_counts_k(int* counts) { if (threadIdx.x < EE) counts[threadIdx.x] = 0; }

__global__ void router_k(const float* __restrict__ p, const float* __restrict__ Wg,
                         int* __restrict__ counts, int* __restrict__ slot_token,
                         int* __restrict__ pair_slot, float* __restrict__ pair_gate)
{
    const int t = blockIdx.x;
    const int tid = threadIdx.x; // 128
    __shared__ float red[EE][128];
    float acc[EE];
#pragma unroll
    for (int e = 0; e < EE; e++) acc[e] = 0.f;
    const float* pr = p + (size_t)t * PP;
    for (int j = tid; j < PP; j += 128) {
        float pv = pr[j];
        const float* wg = Wg + (size_t)j * EE;
#pragma unroll
        for (int e = 0; e < EE; e++) acc[e] += pv * wg[e];
    }
#pragma unroll
    for (int e = 0; e < EE; e++) red[e][tid] = acc[e];
    __syncthreads();
    if (tid == 0) {
        float logit[EE];
        for (int e = 0; e < EE; e++) {
            float s = 0.f;
            for (int i = 0; i < 128; i++) s += red[e][i];
            logit[e] = s;
        }
        int i0 = 0;
        for (int e = 1; e < EE; e++) if (logit[e] > logit[i0]) i0 = e;
        int i1 = (i0 == 0) ? 1 : 0;
        for (int e = 0; e < EE; e++) {
            if (e == i0) continue;
            if (logit[e] > logit[i1]) i1 = e;
        }
        float g0 = 1.f / (1.f + expf(logit[i1] - logit[i0]));
        float g1 = 1.f - g0;
        int s0 = atomicAdd(&counts[i0], 1);
        int s1 = atomicAdd(&counts[i1], 1);
        slot_token[i0 * CAP + s0] = t;
        slot_token[i1 * CAP + s1] = t;
        pair_slot[2 * t]     = i0 * CAP + s0;
        pair_slot[2 * t + 1] = i1 * CAP + s1;
        pair_gate[2 * t]     = g0;
        pair_gate[2 * t + 1] = g1;
    }
}

// ---------------- head: tiled, 32 tokens per block ----------------
#define HKC 128
__global__ __launch_bounds__(928)
void head2_k(const float* __restrict__ hid2, const float* __restrict__ head_w,
             const float* __restrict__ head_b, float* __restrict__ out)
{
    __shared__ float hs[32 * HKC];
    __shared__ float ws[HKC * 30];
    const int tid = threadIdx.x;
    const int tok0 = blockIdx.x * 32;
    const int tokl = tid / OUTN;
    const int o    = tid % OUTN;
    float acc = 0.f;

    for (int kc = 0; kc < HH; kc += HKC) {
        for (int i = tid; i < 32 * HKC; i += 928)
            hs[i] = hid2[(size_t)(tok0 + (i >> 7)) * HH + kc + (i & (HKC - 1))];
        for (int i = tid; i < HKC * OUTN; i += 928) {
            int k = i / OUTN, oo = i % OUTN;
            ws[k * 30 + oo] = head_w[(size_t)(kc + k) * OUTN + oo];
        }
        __syncthreads();
        const float* hrow = hs + tokl * HKC;
#pragma unroll 4
        for (int k = 0; k < HKC; k++)
            acc += hrow[k] * ws[k * 30 + o];
        __syncthreads();
    }
    out[(size_t)(tok0 + tokl) * OUTN + o] = acc + head_b[o];
}

// ---------------- launch ----------------
template <typename T>
static T* symaddr(const void* sym) { void* p = nullptr; cudaGetSymbolAddress(&p, sym); return (T*)p; }

extern "C" void kernel_launch(void* const* d_in, const int* in_sizes, int n_in,
                              void* d_out, int out_size)
{
    const float* x      = (const float*)d_in[0];
    const float* Wproj  = (const float*)d_in[1];
    const float* bproj  = (const float*)d_in[2];
    const float* Wg     = (const float*)d_in[3];
    const float* W1     = (const float*)d_in[4];
    const float* b1     = (const float*)d_in[5];
    const float* W2     = (const float*)d_in[6];
    const float* b2     = (const float*)d_in[7];
    const float* sg_w   = (const float*)d_in[8];
    const float* sg_b   = (const float*)d_in[9];
    const float* su_w   = (const float*)d_in[10];
    const float* su_b   = (const float*)d_in[11];
    const float* sd_w   = (const float*)d_in[12];
    const float* sd_b   = (const float*)d_in[13];
    const float* m1_w   = (const float*)d_in[14];
    const float* m1_b   = (const float*)d_in[15];
    const float* m2_w   = (const float*)d_in[16];
    const float* m2_b   = (const float*)d_in[17];
    const float* head_w = (const float*)d_in[18];
    const float* head_b = (const float*)d_in[19];
    float* out = (float*)d_out;

    static cudaStream_t s1 = nullptr;
    static cudaEvent_t evFork, evP, evW1, evW2, evSw;
    if (!s1) {
        cudaStreamCreateWithFlags(&s1, cudaStreamNonBlocking);
        cudaEventCreateWithFlags(&evFork, cudaEventDisableTiming);
        cudaEventCreateWithFlags(&evP,    cudaEventDisableTiming);
        cudaEventCreateWithFlags(&evW1,   cudaEventDisableTiming);
        cudaEventCreateWithFlags(&evW2,   cudaEventDisableTiming);
        cudaEventCreateWithFlags(&evSw,   cudaEventDisableTiming);
        cudaFuncSetAttribute(mm_gemm<0, false>, cudaFuncAttributeMaxDynamicSharedMemorySize, SMEM_BYTES);
        cudaFuncSetAttribute(mm_gemm<1, false>, cudaFuncAttributeMaxDynamicSharedMemorySize, SMEM_BYTES);
        cudaFuncSetAttribute(mm_gemm<4, false>, cudaFuncAttributeMaxDynamicSharedMemorySize, SMEM_BYTES);
        cudaFuncSetAttribute(mm_gemm<5, false>, cudaFuncAttributeMaxDynamicSharedMemorySize, SMEM_BYTES);
        cudaFuncSetAttribute(mm_gemm<1, true>,  cudaFuncAttributeMaxDynamicSharedMemorySize, SMEM_BYTES);
    }

    __nv_bfloat16 *x_hi = symaddr<__nv_bfloat16>(g_x_hi),  *x_lo = symaddr<__nv_bfloat16>(g_x_lo);
    __nv_bfloat16 *p_hi = symaddr<__nv_bfloat16>(g_p_hi),  *p_lo = symaddr<__nv_bfloat16>(g_p_lo);
    float *p32  = symaddr<float>(g_p32);
    __nv_bfloat16 *h_hi  = symaddr<__nv_bfloat16>(g_h_hi),  *h_lo  = symaddr<__nv_bfloat16>(g_h_lo);
    float *eo32 = symaddr<float>(g_eo32);
    __nv_bfloat16 *su_hi = symaddr<__nv_bfloat16>(g_su_hi), *su_lo = symaddr<__nv_bfloat16>(g_su_lo);
    __nv_bfloat16 *cb_hi = symaddr<__nv_bfloat16>(g_cb_hi), *cb_lo = symaddr<__nv_bfloat16>(g_cb_lo);
    __nv_bfloat16 *h1_hi = symaddr<__nv_bfloat16>(g_h1_hi), *h1_lo = symaddr<__nv_bfloat16>(g_h1_lo);
    float *h232 = symaddr<float>(g_h232);
    __nv_bfloat16 *wp_hi = symaddr<__nv_bfloat16>(g_wp_hi), *wp_lo = symaddr<__nv_bfloat16>(g_wp_lo);
    __nv_bfloat16 *w1_hi = symaddr<__nv_bfloat16>(g_w1_hi), *w1_lo = symaddr<__nv_bfloat16>(g_w1_lo);
    __nv_bfloat16 *w2_hi = symaddr<__nv_bfloat16>(g_w2_hi), *w2_lo = symaddr<__nv_bfloat16>(g_w2_lo);
    __nv_bfloat16 *guw_hi = symaddr<__nv_bfloat16>(g_guw_hi), *guw_lo = symaddr<__nv_bfloat16>(g_guw_lo);
    float *gub = symaddr<float>(g_gub);
    __nv_bfloat16 *sdw_hi = symaddr<__nv_bfloat16>(g_sdw_hi), *sdw_lo = symaddr<__nv_bfloat16>(g_sdw_lo);
    __nv_bfloat16 *m1_hi = symaddr<__nv_bfloat16>(g_m1_hi), *m1_lo = symaddr<__nv_bfloat16>(g_m1_lo);
    __nv_bfloat16 *m2_hi = symaddr<__nv_bfloat16>(g_m2_hi), *m2_lo = symaddr<__nv_bfloat16>(g_m2_lo);
    int *counts = symaddr<int>(g_counts);
    int *stok   = symaddr<int>(g_slot_token);
    int *pslot  = symaddr<int>(g_pair_slot);
    float *pgate = symaddr<float>(g_pair_gate);

    // ---- fork side stream ----
    cudaEventRecord(evFork, 0);
    cudaStreamWaitEvent(s1, evFork, 0);

    // s1: heavy weight transposes (overlap proj GEMM + router)
    convT2_k<1><<<dim3(HH / 128, PP / 32, EE),  256, 0, s1>>>(W1, w1_hi, w1_lo, PP, HH, 0);
    cudaEventRecord(evW1, s1);
    convT2_k<1><<<dim3(PP / 128, HH / 32, EE),  256, 0, s1>>>(W2, w2_hi, w2_lo, HH, PP, 0);
    cudaEventRecord(evW2, s1);
    convT2_k<2><<<dim3(HSH / 128, PP / 32, 1),  256, 0, s1>>>(sg_w, guw_hi, guw_lo, PP, HSH, 0);
    convT2_k<2><<<dim3(HSH / 128, PP / 32, 1),  256, 0, s1>>>(su_w, guw_hi, guw_lo, PP, HSH, 1);
    ileave_bias_k<<<(HSH + 255) / 256, 256, 0, s1>>>(sg_b, su_b, gub, HSH);
    convT2_k<1><<<dim3(PP / 128, HSH / 32, 1),  256, 0, s1>>>(sd_w, sdw_hi, sdw_lo, HSH, PP, 0);
    convT2_k<1><<<dim3(HH / 128, PP / 32, 1),   256, 0, s1>>>(m1_w, m1_hi, m1_lo, PP, HH, 0);
    convT2_k<1><<<dim3(HH / 128, HH / 32, 1),   256, 0, s1>>>(m2_w, m2_hi, m2_lo, HH, HH, 0);

    // main: input split + proj GEMM + router
    conv_split_k<<<(B_TOK * DIN + 255) / 256, 256>>>(x, x_hi, x_lo, (size_t)B_TOK * DIN);
    convT2_k<1><<<dim3(PP / 128, DIN / 32, 1),  256>>>(Wproj, wp_hi, wp_lo, DIN, PP, 0);
    mm_gemm<0, false><<<dim3(PP / BN, B_TOK / BM, 1), NTHR, SMEM_BYTES>>>(
        x_hi, x_lo, wp_hi, wp_lo, bproj, nullptr, p32, p_hi, p_lo,
        nullptr, nullptr, nullptr, nullptr, B_TOK, PP, DIN);
    cudaEventRecord(evP, 0);
    zero_counts_k<<<1, 32>>>(counts);
    router_k<<<B_TOK, 128>>>(p32, Wg, counts, stok, pslot, pgate);

    // s1: fused shared SwiGLU (overlaps expert chain)
    cudaStreamWaitEvent(s1, evP, 0);
    mm_gemm<4, false><<<dim3((2 * HSH) / BN, B_TOK / BM, 1), NTHR, SMEM_BYTES, s1>>>(
        p_hi, p_lo, guw_hi, guw_lo, gub, nullptr, nullptr, su_hi, su_lo,
        nullptr, nullptr, nullptr, nullptr, B_TOK, 2 * HSH, PP);
    cudaEventRecord(evSw, s1);

    // main: expert chain
    cudaStreamWaitEvent(0, evW1, 0);
    mm_gemm<1, true><<<dim3(HH / BN, CAP / BM, EE), NTHR, SMEM_BYTES>>>(
        p_hi, p_lo, w1_hi, w1_lo, b1, nullptr, nullptr, h_hi, h_lo,
        counts, stok, nullptr, nullptr, CAP, HH, PP);
    cudaStreamWaitEvent(0, evW2, 0);
    mm_gemm<0, false><<<dim3(PP / BN, CAP / BM, EE), NTHR, SMEM_BYTES>>>(
        h_hi, h_lo, w2_hi, w2_lo, b2, nullptr, eo32, nullptr, nullptr,
        counts, nullptr, nullptr, nullptr, CAP, PP, HH);

    // join: down proj with fused MoE combine in epilogue (MODE 5)
    cudaStreamWaitEvent(0, evSw, 0);
    mm_gemm<5, false><<<dim3(PP / BN, B_TOK / BM, 1), NTHR, SMEM_BYTES>>>(
        su_hi, su_lo, sdw_hi, sdw_lo, sd_b, eo32, nullptr, cb_hi, cb_lo,
        nullptr, nullptr, pslot, pgate, B_TOK, PP, HSH);
    // output MLP
    mm_gemm<1, false><<<dim3(HH / BN, B_TOK / BM, 1), NTHR, SMEM_BYTES>>>(
        cb_hi, cb_lo, m1_hi, m1_lo, m1_b, nullptr, nullptr, h1_hi, h1_lo,
        nullptr, nullptr, nullptr, nullptr, B_TOK, HH, PP);
    mm_gemm<0, false><<<dim3(HH / BN, B_TOK / BM, 1), NTHR, SMEM_BYTES>>>(
        h1_hi, h1_lo, m2_hi, m2_lo, m2_b, nullptr, h232, nullptr, nullptr,
        nullptr, nullptr, nullptr, nullptr, B_TOK, HH, HH);
    // head
    head2_k<<<B_TOK / 32, 928>>>(h232, head_w, head_b, out);
}

// round 16
// speedup vs baseline: 1.0157x; 1.0052x over previous
#include <cuda_runtime.h>
#include <cuda_bf16.h>
#include <math.h>
#include <stdint.h>

// ---------------- problem constants ----------------
#define B_TOK 4096
#define DIN   512
#define PP    1024
#define HH    2048
#define EE    8
#define HSH   4096
#define OUTN  29
#define CAP   4096

// ---------------- big GEMM config (proven) ----------------
#define BM 128
#define BN 256
#define BKC 32
#define ROWB 80
#define OFF_AH 0
#define OFF_AL (128 * ROWB)
#define OFF_BH (256 * ROWB)
#define OFF_BL (256 * ROWB + 256 * ROWB)
#define STAGE_BYTES (768 * ROWB)
#define NSTAGE 3
#define SMEM_BYTES (NSTAGE * STAGE_BYTES)
#define NTHR 512
#define MHALF (B_TOK / 2)

// ---------------- PTX helpers ----------------
__device__ __forceinline__ uint32_t smem_u32(const void* p) {
    uint32_t a;
    asm("{ .reg .u64 t; cvta.to.shared.u64 t, %1; cvt.u32.u64 %0, t; }" : "=r"(a) : "l"(p));
    return a;
}
#define CP16(dst, src) asm volatile("cp.async.cg.shared.global [%0], [%1], 16;" :: "r"(dst), "l"(src) : "memory")
#define CP_COMMIT()    asm volatile("cp.async.commit_group;" ::: "memory")

#define LDSM4(r, addr) \
    asm volatile("ldmatrix.sync.aligned.m8n8.x4.shared.b16 {%0,%1,%2,%3}, [%4];" \
        : "=r"((r)[0]), "=r"((r)[1]), "=r"((r)[2]), "=r"((r)[3]) : "r"(addr))

#define MMA_BF16(c, a, b0, b1) \
    asm volatile("mma.sync.aligned.m16n8k16.row.col.f32.bf16.bf16.f32 " \
        "{%0,%1,%2,%3}, {%4,%5,%6,%7}, {%8,%9}, {%0,%1,%2,%3};" \
        : "+f"((c)[0]), "+f"((c)[1]), "+f"((c)[2]), "+f"((c)[3]) \
        : "r"((a)[0]), "r"((a)[1]), "r"((a)[2]), "r"((a)[3]), "r"(b0), "r"(b1))

// ---------------- scratch (device globals) ----------------
#define DEV __device__ __align__(128)
DEV __nv_bfloat16 g_x_hi [B_TOK * DIN],   g_x_lo [B_TOK * DIN];
DEV __nv_bfloat16 g_p_hi [B_TOK * PP],    g_p_lo [B_TOK * PP];
DEV float         g_p32  [B_TOK * PP];
DEV __nv_bfloat16 g_h_hi [(size_t)EE * CAP * HH], g_h_lo [(size_t)EE * CAP * HH];
DEV float         g_eo32 [(size_t)EE * CAP * PP];
DEV __nv_bfloat16 g_su_hi[(size_t)B_TOK * HSH],   g_su_lo[(size_t)B_TOK * HSH];
DEV __nv_bfloat16 g_cb_hi[B_TOK * PP],    g_cb_lo[B_TOK * PP];
DEV __nv_bfloat16 g_h1_hi[B_TOK * HH],    g_h1_lo[B_TOK * HH];
DEV float         g_h232 [B_TOK * HH];
DEV __nv_bfloat16 g_wp_hi [PP * DIN],     g_wp_lo [PP * DIN];
DEV __nv_bfloat16 g_w1_hi [EE * HH * PP], g_w1_lo [EE * HH * PP];
DEV __nv_bfloat16 g_w2_hi [EE * PP * HH], g_w2_lo [EE * PP * HH];
DEV __nv_bfloat16 g_guw_hi[(size_t)2 * HSH * PP], g_guw_lo[(size_t)2 * HSH * PP];
DEV float         g_gub   [2 * HSH];
DEV __nv_bfloat16 g_sdw_hi[PP * HSH],     g_sdw_lo[PP * HSH];
DEV __nv_bfloat16 g_m1_hi [HH * PP],      g_m1_lo [HH * PP];
DEV __nv_bfloat16 g_m2_hi [HH * HH],      g_m2_lo [HH * HH];
DEV int   g_counts[EE];
DEV int   g_slot_token[EE * CAP];
DEV int   g_pair_slot[B_TOK * 2];
DEV float g_pair_gate[B_TOK * 2];

__device__ __forceinline__ float silu_f(float x) { return x / (1.0f + expf(-x)); }

// ---------------- stage fill (512 threads): A 128 rows + B 256 rows, hi+lo ----------------
template<bool GATHER>
__device__ __forceinline__ void fill_stage(uint32_t st, int tid,
    const char* Ah, const char* Al, const char* Bh, const char* Bl,
    size_t Kb, long rowA0, long rowB0, const int* __restrict__ tokRow, size_t kByte)
{
    {
        int row = tid >> 2, ch = tid & 3;
        uint32_t d = st + row * ROWB + ch * 16;
        long arow = GATHER ? (long)tokRow[row] : (rowA0 + row);
        size_t s = (size_t)arow * Kb + kByte + ch * 16;
        CP16(d + OFF_AH, Ah + s);
        CP16(d + OFF_AL, Al + s);
    }
#pragma unroll
    for (int i = 0; i < 2; i++) {
        int p = tid + (i << 9);
        int row = p >> 2, ch = p & 3;
        uint32_t d = st + row * ROWB + ch * 16;
        size_t s = (size_t)(rowB0 + row) * Kb + kByte + ch * 16;
        CP16(d + OFF_BH, Bh + s);
        CP16(d + OFF_BL, Bl + s);
    }
    CP_COMMIT();
}

// ---------------- bf16-split x3 GEMM, 16 warps, warp tile 32x64 ----------------
// MODE: 0=+bias 1=silu(+bias) 3=(+bias)+extra 4=fused SwiGLU pairs
// MODE 5: (+bias) + g0*eo[s0,col] + g1*eo[s1,col]   (fused MoE combine, extra=eo32)
template<int MODE, bool GATHER>
__global__ __launch_bounds__(NTHR, 1)
void mm_gemm(const __nv_bfloat16* __restrict__ Ahi, const __nv_bfloat16* __restrict__ Alo,
             const __nv_bfloat16* __restrict__ Bhi, const __nv_bfloat16* __restrict__ Blo,
             const float* __restrict__ bias, const float* __restrict__ extra,
             float* __restrict__ C32, __nv_bfloat16* __restrict__ Chi,
             __nv_bfloat16* __restrict__ Clo,
             const int* __restrict__ counts, const int* __restrict__ stok,
             const int* __restrict__ pslot, const float* __restrict__ pgate,
             int capRows, int N, int K)
{
    const int z  = blockIdx.z;
    const int m0 = blockIdx.y * BM;
    const int n0 = blockIdx.x * BN;
    int cnt = capRows;
    if (counts) { cnt = counts[z]; if (m0 >= cnt) return; }

    extern __shared__ __align__(128) char smem[];
    const uint32_t sb = smem_u32(smem);
    const int tid = threadIdx.x, lane = tid & 31, wid = tid >> 5;
    const int warp_m = wid & 3;
    const int warp_n = wid >> 2;

    const size_t Kb = (size_t)K * 2;
    const long rowA0 = (long)z * capRows + m0;
    const long rowB0 = (long)z * N + n0;
    const int* tokRow = GATHER ? (stok + z * CAP + m0) : nullptr;
    const int  C = K / BKC;

    float acc[2][8][4];
#pragma unroll
    for (int i = 0; i < 2; i++)
#pragma unroll
        for (int j = 0; j < 8; j++)
#pragma unroll
            for (int q = 0; q < 4; q++) acc[i][j][q] = 0.f;

    const char* Ah = (const char*)Ahi; const char* Al = (const char*)Alo;
    const char* Bh = (const char*)Bhi; const char* Bl = (const char*)Blo;

    fill_stage<GATHER>(sb, tid, Ah, Al, Bh, Bl, Kb, rowA0, rowB0, tokRow, 0);
    if (C > 1) fill_stage<GATHER>(sb + STAGE_BYTES, tid, Ah, Al, Bh, Bl, Kb, rowA0, rowB0, tokRow, 64);

    const int lm = lane & 15;
    const int lkb = (lane >> 4) << 4;

    for (int c = 0; c < C; c++) {
        if (c + 2 < C) asm volatile("cp.async.wait_group 1;" ::: "memory");
        else           asm volatile("cp.async.wait_group 0;" ::: "memory");
        __syncthreads();
        if (c + 2 < C)
            fill_stage<GATHER>(sb + ((c + 2) % NSTAGE) * STAGE_BYTES, tid, Ah, Al, Bh, Bl,
                               Kb, rowA0, rowB0, tokRow, (size_t)(c + 2) * 64);

        const uint32_t stg = sb + (c % NSTAGE) * STAGE_BYTES;
#pragma unroll
        for (int kk = 0; kk < 2; kk++) {
            const uint32_t kb = kk * 32 + lkb;
            uint32_t a_h[2][4], a_l[2][4];
#pragma unroll
            for (int mt = 0; mt < 2; mt++) {
                uint32_t ad = stg + (warp_m * 32 + mt * 16 + lm) * ROWB + kb;
                LDSM4(a_h[mt], ad + OFF_AH);
                LDSM4(a_l[mt], ad + OFF_AL);
            }
#pragma unroll
            for (int n2 = 0; n2 < 4; n2++) {
                uint32_t b_h[4], b_l[4];
                uint32_t bd = stg + (warp_n * 64 + n2 * 16 + lm) * ROWB + kb;
                LDSM4(b_h, bd + OFF_BH);
                LDSM4(b_l, bd + OFF_BL);
#pragma unroll
                for (int mt = 0; mt < 2; mt++)
#pragma unroll
                    for (int o = 0; o < 2; o++) {
                        const int nt = n2 * 2 + o;
                        MMA_BF16(acc[mt][nt], a_h[mt], b_h[o], b_h[o + 2]);
                        MMA_BF16(acc[mt][nt], a_h[mt], b_l[o], b_l[o + 2]);
                        MMA_BF16(acc[mt][nt], a_l[mt], b_h[o], b_h[o + 2]);
                    }
            }
        }
    }

    const float* biasz = bias + (size_t)z * N;
#pragma unroll
    for (int mt = 0; mt < 2; mt++) {
#pragma unroll
        for (int half = 0; half < 2; half++) {
            const int rtile = warp_m * 32 + mt * 16 + (lane >> 2) + half * 8;
            if (m0 + rtile >= cnt) continue;
            const size_t gr = (size_t)z * capRows + m0 + rtile;
            long e0base = 0, e1base = 0;
            float mg0 = 0.f, mg1 = 0.f;
            if (MODE == 5) {
                const int s0 = pslot[2 * gr], s1p = pslot[2 * gr + 1];
                mg0 = pgate[2 * gr]; mg1 = pgate[2 * gr + 1];
                e0base = (long)s0 * PP;
                e1base = (long)s1p * PP;
            }
#pragma unroll
            for (int nt = 0; nt < 8; nt++) {
                const int col = n0 + warp_n * 64 + nt * 8 + (lane & 3) * 2;
                float v0 = acc[mt][nt][half * 2 + 0] + biasz[col];
                float v1 = acc[mt][nt][half * 2 + 1] + biasz[col + 1];
                if (MODE == 4) {
                    float w = silu_f(v0) * v1;
                    __nv_bfloat16 h = __float2bfloat16(w);
                    const size_t o = gr * (size_t)(N >> 1) + (col >> 1);
                    Chi[o] = h;
                    Clo[o] = __float2bfloat16(w - __bfloat162float(h));
                    continue;
                }
                if (MODE == 1) { v0 = silu_f(v0); v1 = silu_f(v1); }
                if (MODE == 3) {
                    const float2 e = *(const float2*)&extra[gr * N + col];
                    v0 += e.x; v1 += e.y;
                }
                if (MODE == 5) {
                    const float2 e0 = *(const float2*)&extra[e0base + col];
                    const float2 e1 = *(const float2*)&extra[e1base + col];
                    float moe0 = mg0 * e0.x + mg1 * e1.x;
                    float moe1 = mg0 * e0.y + mg1 * e1.y;
                    v0 += moe0; v1 += moe1;
                }
                if (C32) { float2 w = {v0, v1}; *(float2*)&C32[gr * N + col] = w; }
                if (Chi) {
                    __nv_bfloat16 h0 = __float2bfloat16(v0);
                    __nv_bfloat16 h1 = __float2bfloat16(v1);
                    __nv_bfloat162 hp; hp.x = h0; hp.y = h1;
                    *(__nv_bfloat162*)&Chi[gr * N + col] = hp;
                    __nv_bfloat162 lp;
                    lp.x = __float2bfloat16(v0 - __bfloat162float(h0));
                    lp.y = __float2bfloat16(v1 - __bfloat162float(h1));
                    *(__nv_bfloat162*)&Clo[gr * N + col] = lp;
                }
            }
        }
    }
}

// ---------------- small kernels ----------------
__global__ void conv_split_k(const float* __restrict__ in, __nv_bfloat16* __restrict__ hi,
                             __nv_bfloat16* __restrict__ lo, size_t n)
{
    size_t i = (size_t)blockIdx.x * blockDim.x + threadIdx.x;
    if (i >= n) return;
    float v = in[i];
    __nv_bfloat16 h = __float2bfloat16(v);
    hi[i] = h;
    lo[i] = __float2bfloat16(v - __bfloat162float(h));
}

template<int RMUL>
__global__ __launch_bounds__(256)
void convT2_k(const float* __restrict__ W, __nv_bfloat16* __restrict__ hi,
              __nv_bfloat16* __restrict__ lo, int K, int N, int radd)
{
    __shared__ float t[32][129];
    const int k0 = blockIdx.y * 32, n0 = blockIdx.x * 128;
    const float* Wz = W + (size_t)blockIdx.z * K * N;
    const int tid = threadIdx.x;
    {
        const int c = tid & 127;
        for (int r = tid >> 7; r < 32; r += 2)
            t[r][c] = Wz[(size_t)(k0 + r) * N + n0 + c];
    }
    __syncthreads();
    const size_t zbase = (size_t)blockIdx.z * N * RMUL;
    for (int idx = tid; idx < 128 * 16; idx += 256) {
        const int n = idx >> 4, kp = idx & 15;
        float v0 = t[kp * 2][n], v1 = t[kp * 2 + 1][n];
        __nv_bfloat16 h0 = __float2bfloat16(v0), h1 = __float2bfloat16(v1);
        __nv_bfloat162 hp; hp.x = h0; hp.y = h1;
        __nv_bfloat162 lp;
        lp.x = __float2bfloat16(v0 - __bfloat162float(h0));
        lp.y = __float2bfloat16(v1 - __bfloat162float(h1));
        const size_t orow = zbase + (size_t)(n0 + n) * RMUL + radd;
        const size_t o = orow * K + k0 + kp * 2;
        *(__nv_bfloat162*)&hi[o] = hp;
        *(__nv_bfloat162*)&lo[o] = lp;
    }
}

__global__ void ileave_bias_k(const float* __restrict__ a, const float* __restrict__ b,
                              float* __restrict__ o, int n)
{
    int i = blockIdx.x * 256 + threadIdx.x;
    if (i < n) { o[2 * i] = a[i]; o[2 * i + 1] = b[i]; }
}

__global__ void zero_counts_k(int* counts) { if (threadIdx.x < EE) counts[threadIdx.x] = 0; }

__global__ void router_k(const float* __restrict__ p, const float* __restrict__ Wg,
                         int* __restrict__ counts, int* __restrict__ slot_token,
                         int* __restrict__ pair_slot, float* __restrict__ pair_gate)
{
    const int t = blockIdx.x;
    const int tid = threadIdx.x; // 128
    __shared__ float red[EE][128];
    float acc[EE];
#pragma unroll
    for (int e = 0; e < EE; e++) acc[e] = 0.f;
    const float* pr = p + (size_t)t * PP;
    for (int j = tid; j < PP; j += 128) {
        float pv = pr[j];
        const float* wg = Wg + (size_t)j * EE;
#pragma unroll
        for (int e = 0; e < EE; e++) acc[e] += pv * wg[e];
    }
#pragma unroll
    for (int e = 0; e < EE; e++) red[e][tid] = acc[e];
    __syncthreads();
    if (tid == 0) {
        float logit[EE];
        for (int e = 0; e < EE; e++) {
            float s = 0.f;
            for (int i = 0; i < 128; i++) s += red[e][i];
            logit[e] = s;
        }
        int i0 = 0;
        for (int e = 1; e < EE; e++) if (logit[e] > logit[i0]) i0 = e;
        int i1 = (i0 == 0) ? 1 : 0;
        for (int e = 0; e < EE; e++) {
            if (e == i0) continue;
            if (logit[e] > logit[i1]) i1 = e;
        }
        float g0 = 1.f / (1.f + expf(logit[i1] - logit[i0]));
        float g1 = 1.f - g0;
        int s0 = atomicAdd(&counts[i0], 1);
        int s1 = atomicAdd(&counts[i1], 1);
        slot_token[i0 * CAP + s0] = t;
        slot_token[i1 * CAP + s1] = t;
        pair_slot[2 * t]     = i0 * CAP + s0;
        pair_slot[2 * t + 1] = i1 * CAP + s1;
        pair_gate[2 * t]     = g0;
        pair_gate[2 * t + 1] = g1;
    }
}

// ---------------- head: tiled, 32 tokens per block ----------------
#define HKC 128
__global__ __launch_bounds__(928)
void head2_k(const float* __restrict__ hid2, const float* __restrict__ head_w,
             const float* __restrict__ head_b, float* __restrict__ out)
{
    __shared__ float hs[32 * HKC];
    __shared__ float ws[HKC * 30];
    const int tid = threadIdx.x;
    const int tok0 = blockIdx.x * 32;
    const int tokl = tid / OUTN;
    const int o    = tid % OUTN;
    float acc = 0.f;

    for (int kc = 0; kc < HH; kc += HKC) {
        for (int i = tid; i < 32 * HKC; i += 928)
            hs[i] = hid2[(size_t)(tok0 + (i >> 7)) * HH + kc + (i & (HKC - 1))];
        for (int i = tid; i < HKC * OUTN; i += 928) {
            int k = i / OUTN, oo = i % OUTN;
            ws[k * 30 + oo] = head_w[(size_t)(kc + k) * OUTN + oo];
        }
        __syncthreads();
        const float* hrow = hs + tokl * HKC;
#pragma unroll 4
        for (int k = 0; k < HKC; k++)
            acc += hrow[k] * ws[k * 30 + o];
        __syncthreads();
    }
    out[(size_t)(tok0 + tokl) * OUTN + o] = acc + head_b[o];
}

// ---------------- launch ----------------
template <typename T>
static T* symaddr(const void* sym) { void* p = nullptr; cudaGetSymbolAddress(&p, sym); return (T*)p; }

extern "C" void kernel_launch(void* const* d_in, const int* in_sizes, int n_in,
                              void* d_out, int out_size)
{
    const float* x      = (const float*)d_in[0];
    const float* Wproj  = (const float*)d_in[1];
    const float* bproj  = (const float*)d_in[2];
    const float* Wg     = (const float*)d_in[3];
    const float* W1     = (const float*)d_in[4];
    const float* b1     = (const float*)d_in[5];
    const float* W2     = (const float*)d_in[6];
    const float* b2     = (const float*)d_in[7];
    const float* sg_w   = (const float*)d_in[8];
    const float* sg_b   = (const float*)d_in[9];
    const float* su_w   = (const float*)d_in[10];
    const float* su_b   = (const float*)d_in[11];
    const float* sd_w   = (const float*)d_in[12];
    const float* sd_b   = (const float*)d_in[13];
    const float* m1_w   = (const float*)d_in[14];
    const float* m1_b   = (const float*)d_in[15];
    const float* m2_w   = (const float*)d_in[16];
    const float* m2_b   = (const float*)d_in[17];
    const float* head_w = (const float*)d_in[18];
    const float* head_b = (const float*)d_in[19];
    float* out = (float*)d_out;

    static cudaStream_t s1 = nullptr;
    static cudaEvent_t evFork, evP, evW1, evW2, evSw, evE2, evEnd;
    if (!s1) {
        cudaStreamCreateWithFlags(&s1, cudaStreamNonBlocking);
        cudaEventCreateWithFlags(&evFork, cudaEventDisableTiming);
        cudaEventCreateWithFlags(&evP,    cudaEventDisableTiming);
        cudaEventCreateWithFlags(&evW1,   cudaEventDisableTiming);
        cudaEventCreateWithFlags(&evW2,   cudaEventDisableTiming);
        cudaEventCreateWithFlags(&evSw,   cudaEventDisableTiming);
        cudaEventCreateWithFlags(&evE2,   cudaEventDisableTiming);
        cudaEventCreateWithFlags(&evEnd,  cudaEventDisableTiming);
        cudaFuncSetAttribute(mm_gemm<0, false>, cudaFuncAttributeMaxDynamicSharedMemorySize, SMEM_BYTES);
        cudaFuncSetAttribute(mm_gemm<1, false>, cudaFuncAttributeMaxDynamicSharedMemorySize, SMEM_BYTES);
        cudaFuncSetAttribute(mm_gemm<4, false>, cudaFuncAttributeMaxDynamicSharedMemorySize, SMEM_BYTES);
        cudaFuncSetAttribute(mm_gemm<5, false>, cudaFuncAttributeMaxDynamicSharedMemorySize, SMEM_BYTES);
        cudaFuncSetAttribute(mm_gemm<1, true>,  cudaFuncAttributeMaxDynamicSharedMemorySize, SMEM_BYTES);
    }

    __nv_bfloat16 *x_hi = symaddr<__nv_bfloat16>(g_x_hi),  *x_lo = symaddr<__nv_bfloat16>(g_x_lo);
    __nv_bfloat16 *p_hi = symaddr<__nv_bfloat16>(g_p_hi),  *p_lo = symaddr<__nv_bfloat16>(g_p_lo);
    float *p32  = symaddr<float>(g_p32);
    __nv_bfloat16 *h_hi  = symaddr<__nv_bfloat16>(g_h_hi),  *h_lo  = symaddr<__nv_bfloat16>(g_h_lo);
    float *eo32 = symaddr<float>(g_eo32);
    __nv_bfloat16 *su_hi = symaddr<__nv_bfloat16>(g_su_hi), *su_lo = symaddr<__nv_bfloat16>(g_su_lo);
    __nv_bfloat16 *cb_hi = symaddr<__nv_bfloat16>(g_cb_hi), *cb_lo = symaddr<__nv_bfloat16>(g_cb_lo);
    __nv_bfloat16 *h1_hi = symaddr<__nv_bfloat16>(g_h1_hi), *h1_lo = symaddr<__nv_bfloat16>(g_h1_lo);
    float *h232 = symaddr<float>(g_h232);
    __nv_bfloat16 *wp_hi = symaddr<__nv_bfloat16>(g_wp_hi), *wp_lo = symaddr<__nv_bfloat16>(g_wp_lo);
    __nv_bfloat16 *w1_hi = symaddr<__nv_bfloat16>(g_w1_hi), *w1_lo = symaddr<__nv_bfloat16>(g_w1_lo);
    __nv_bfloat16 *w2_hi = symaddr<__nv_bfloat16>(g_w2_hi), *w2_lo = symaddr<__nv_bfloat16>(g_w2_lo);
    __nv_bfloat16 *guw_hi = symaddr<__nv_bfloat16>(g_guw_hi), *guw_lo = symaddr<__nv_bfloat16>(g_guw_lo);
    float *gub = symaddr<float>(g_gub);
    __nv_bfloat16 *sdw_hi = symaddr<__nv_bfloat16>(g_sdw_hi), *sdw_lo = symaddr<__nv_bfloat16>(g_sdw_lo);
    __nv_bfloat16 *m1_hi = symaddr<__nv_bfloat16>(g_m1_hi), *m1_lo = symaddr<__nv_bfloat16>(g_m1_lo);
    __nv_bfloat16 *m2_hi = symaddr<__nv_bfloat16>(g_m2_hi), *m2_lo = symaddr<__nv_bfloat16>(g_m2_lo);
    int *counts = symaddr<int>(g_counts);
    int *stok   = symaddr<int>(g_slot_token);
    int *pslot  = symaddr<int>(g_pair_slot);
    float *pgate = symaddr<float>(g_pair_gate);

    // ---- fork side stream ----
    cudaEventRecord(evFork, 0);
    cudaStreamWaitEvent(s1, evFork, 0);

    // s1: heavy weight transposes (overlap proj GEMM + router)
    convT2_k<1><<<dim3(HH / 128, PP / 32, EE),  256, 0, s1>>>(W1, w1_hi, w1_lo, PP, HH, 0);
    cudaEventRecord(evW1, s1);
    convT2_k<1><<<dim3(PP / 128, HH / 32, EE),  256, 0, s1>>>(W2, w2_hi, w2_lo, HH, PP, 0);
    cudaEventRecord(evW2, s1);
    convT2_k<2><<<dim3(HSH / 128, PP / 32, 1),  256, 0, s1>>>(sg_w, guw_hi, guw_lo, PP, HSH, 0);
    convT2_k<2><<<dim3(HSH / 128, PP / 32, 1),  256, 0, s1>>>(su_w, guw_hi, guw_lo, PP, HSH, 1);
    ileave_bias_k<<<(HSH + 255) / 256, 256, 0, s1>>>(sg_b, su_b, gub, HSH);
    convT2_k<1><<<dim3(PP / 128, HSH / 32, 1),  256, 0, s1>>>(sd_w, sdw_hi, sdw_lo, HSH, PP, 0);
    convT2_k<1><<<dim3(HH / 128, PP / 32, 1),   256, 0, s1>>>(m1_w, m1_hi, m1_lo, PP, HH, 0);
    convT2_k<1><<<dim3(HH / 128, HH / 32, 1),   256, 0, s1>>>(m2_w, m2_hi, m2_lo, HH, HH, 0);

    // main: input split + proj GEMM + router
    conv_split_k<<<(B_TOK * DIN + 255) / 256, 256>>>(x, x_hi, x_lo, (size_t)B_TOK * DIN);
    convT2_k<1><<<dim3(PP / 128, DIN / 32, 1),  256>>>(Wproj, wp_hi, wp_lo, DIN, PP, 0);
    mm_gemm<0, false><<<dim3(PP / BN, B_TOK / BM, 1), NTHR, SMEM_BYTES>>>(
        x_hi, x_lo, wp_hi, wp_lo, bproj, nullptr, p32, p_hi, p_lo,
        nullptr, nullptr, nullptr, nullptr, B_TOK, PP, DIN);
    cudaEventRecord(evP, 0);
    zero_counts_k<<<1, 32>>>(counts);
    router_k<<<B_TOK, 128>>>(p32, Wg, counts, stok, pslot, pgate);

    // s1: fused shared SwiGLU (overlaps expert chain)
    cudaStreamWaitEvent(s1, evP, 0);
    mm_gemm<4, false><<<dim3((2 * HSH) / BN, B_TOK / BM, 1), NTHR, SMEM_BYTES, s1>>>(
        p_hi, p_lo, guw_hi, guw_lo, gub, nullptr, nullptr, su_hi, su_lo,
        nullptr, nullptr, nullptr, nullptr, B_TOK, 2 * HSH, PP);
    cudaEventRecord(evSw, s1);

    // main: expert chain
    cudaStreamWaitEvent(0, evW1, 0);
    mm_gemm<1, true><<<dim3(HH / BN, CAP / BM, EE), NTHR, SMEM_BYTES>>>(
        p_hi, p_lo, w1_hi, w1_lo, b1, nullptr, nullptr, h_hi, h_lo,
        counts, stok, nullptr, nullptr, CAP, HH, PP);
    cudaStreamWaitEvent(0, evW2, 0);
    mm_gemm<0, false><<<dim3(PP / BN, CAP / BM, EE), NTHR, SMEM_BYTES>>>(
        h_hi, h_lo, w2_hi, w2_lo, b2, nullptr, eo32, nullptr, nullptr,
        counts, nullptr, nullptr, nullptr, CAP, PP, HH);
    cudaEventRecord(evE2, 0);

    // ---- end-chain pipelined by M-halves across both streams ----
    // half A (rows [0, 2048)) on main; half B (rows [2048, 4096)) on s1
    cudaStreamWaitEvent(0, evSw, 0);        // main: needs su (s1)
    cudaStreamWaitEvent(s1, evE2, 0);       // s1:   needs eo32 (main)

    // down proj (MODE 5: fused MoE combine)
    mm_gemm<5, false><<<dim3(PP / BN, MHALF / BM, 1), NTHR, SMEM_BYTES>>>(
        su_hi, su_lo, sdw_hi, sdw_lo, sd_b, eo32, nullptr, cb_hi, cb_lo,
        nullptr, nullptr, pslot, pgate, MHALF, PP, HSH);
    mm_gemm<5, false><<<dim3(PP / BN, MHALF / BM, 1), NTHR, SMEM_BYTES, s1>>>(
        su_hi + (size_t)MHALF * HSH, su_lo + (size_t)MHALF * HSH,
        sdw_hi, sdw_lo, sd_b, eo32, nullptr,
        cb_hi + (size_t)MHALF * PP, cb_lo + (size_t)MHALF * PP,
        nullptr, nullptr, pslot + 2 * MHALF, pgate + 2 * MHALF, MHALF, PP, HSH);

    // m1
    mm_gemm<1, false><<<dim3(HH / BN, MHALF / BM, 1), NTHR, SMEM_BYTES>>>(
        cb_hi, cb_lo, m1_hi, m1_lo, m1_b, nullptr, nullptr, h1_hi, h1_lo,
        nullptr, nullptr, nullptr, nullptr, MHALF, HH, PP);
    mm_gemm<1, false><<<dim3(HH / BN, MHALF / BM, 1), NTHR, SMEM_BYTES, s1>>>(
        cb_hi + (size_t)MHALF * PP, cb_lo + (size_t)MHALF * PP,
        m1_hi, m1_lo, m1_b, nullptr, nullptr,
        h1_hi + (size_t)MHALF * HH, h1_lo + (size_t)MHALF * HH,
        nullptr, nullptr, nullptr, nullptr, MHALF, HH, PP);

    // m2
    mm_gemm<0, false><<<dim3(HH / BN, MHALF / BM, 1), NTHR, SMEM_BYTES>>>(
        h1_hi, h1_lo, m2_hi, m2_lo, m2_b, nullptr, h232, nullptr, nullptr,
        nullptr, nullptr, nullptr, nullptr, MHALF, HH, HH);
    mm_gemm<0, false><<<dim3(HH / BN, MHALF / BM, 1), NTHR, SMEM_BYTES, s1>>>(
        h1_hi + (size_t)MHALF * HH, h1_lo + (size_t)MHALF * HH,
        m2_hi, m2_lo, m2_b, nullptr, h232 + (size_t)MHALF * HH, nullptr, nullptr,
        nullptr, nullptr, nullptr, nullptr, MHALF, HH, HH);

    // head halves
    head2_k<<<MHALF / 32, 928>>>(h232, head_w, head_b, out);
    head2_k<<<MHALF / 32, 928, 0, s1>>>(h232 + (size_t)MHALF * HH, head_w, head_b,
                                        out + (size_t)MHALF * OUTN);

    // join s1 back into main before return
    cudaEventRecord(evEnd, s1);
    cudaStreamWaitEvent(0, evEnd, 0);
}